// round 4
// baseline (speedup 1.0000x reference)
#include <cuda_runtime.h>
#include <cuda_bf16.h>
#include <cstdint>
#include <math.h>

// Problem constants
#define BB 128
#define HH 16
#define WW 48
#define DD 512
#define UU 512
#define HW (HH*WW)          // 768
#define MM (BB*HW)          // 98304

// ---------------------------------------------------------------------------
// Device globals (scratch; no allocation allowed)
// ---------------------------------------------------------------------------
__device__ float         g_dec_proj[BB*UU];       // dec @ W2 + b1 + b2
__device__ float         g_part[2*MM];            // partial scores per N-half
__device__ float         g_ctx_part[4*BB*DD];     // context partials
__device__ __nv_bfloat16 g_W1T_hi[UU*DD];         // W1^T split-hi [u][k]
__device__ __nv_bfloat16 g_W1T_lo[UU*DD];         // W1^T split-lo [u][k]

// ---------------------------------------------------------------------------
// Helpers
// ---------------------------------------------------------------------------
__device__ __forceinline__ uint32_t smem_u32(const void* p) {
    uint32_t a;
    asm("{ .reg .u64 t; cvta.to.shared.u64 t, %1; cvt.u32.u64 %0, t; }"
        : "=r"(a) : "l"(p));
    return a;
}

__device__ __forceinline__ void cp16(uint32_t s, const void* g) {
    asm volatile("cp.async.cg.shared.global [%0], [%1], 16;"
                 :: "r"(s), "l"(g) : "memory");
}
__device__ __forceinline__ void cp_commit() {
    asm volatile("cp.async.commit_group;" ::: "memory");
}
#define CP_WAIT(n) asm volatile("cp.async.wait_group %0;" :: "n"(n) : "memory")

__device__ __forceinline__ void ldsm4(uint32_t* r, uint32_t addr) {
    asm volatile("ldmatrix.sync.aligned.m8n8.x4.shared.b16 {%0,%1,%2,%3}, [%4];"
                 : "=r"(r[0]), "=r"(r[1]), "=r"(r[2]), "=r"(r[3]) : "r"(addr));
}

__device__ __forceinline__ void mma_bf16(float* c, const uint32_t* a,
                                         uint32_t b0, uint32_t b1) {
    asm volatile("mma.sync.aligned.m16n8k16.row.col.f32.bf16.bf16.f32 "
                 "{%0,%1,%2,%3}, {%4,%5,%6,%7}, {%8,%9}, {%0,%1,%2,%3};"
                 : "+f"(c[0]), "+f"(c[1]), "+f"(c[2]), "+f"(c[3])
                 : "r"(a[0]), "r"(a[1]), "r"(a[2]), "r"(a[3]),
                   "r"(b0), "r"(b1));
}

// ---------------------------------------------------------------------------
// K0: W1 -> transposed bf16 hi/lo splits  (g_W1T_*[u][k] = split(W1[k][u]))
// ---------------------------------------------------------------------------
__global__ void prep_w1_kernel(const float* __restrict__ W1) {
    int idx = blockIdx.x * 256 + threadIdx.x;    // 0..262143
    int k = idx >> 9, u = idx & 511;
    float x = W1[idx];
    __nv_bfloat16 h = __float2bfloat16(x);
    g_W1T_hi[u*DD + k] = h;
    g_W1T_lo[u*DD + k] = __float2bfloat16(x - __bfloat162float(h));
}

// ---------------------------------------------------------------------------
// K1: dec_proj[b,u] = sum_d dec[b,d]*W2[d,u] + W1_b[u] + W2_b[u]
// grid 32 (4 batches each), block 512.
// ---------------------------------------------------------------------------
__global__ __launch_bounds__(512) void dec_proj_kernel(const float* __restrict__ dec,
                                                       const float* __restrict__ W2,
                                                       const float* __restrict__ b1,
                                                       const float* __restrict__ b2) {
    __shared__ float s_dec[4][DD];
    int b0 = blockIdx.x * 4;
    int t = threadIdx.x;
    #pragma unroll
    for (int i = 0; i < 4; i++) s_dec[i][t] = dec[(b0 + i)*DD + t];
    __syncthreads();
    float bias = b1[t] + b2[t];
    float a0 = bias, a1 = bias, a2 = bias, a3 = bias;
    #pragma unroll 8
    for (int d = 0; d < DD; d++) {
        float w = W2[(size_t)d*UU + t];
        a0 += s_dec[0][d] * w;
        a1 += s_dec[1][d] * w;
        a2 += s_dec[2][d] * w;
        a3 += s_dec[3][d] * w;
    }
    g_dec_proj[(b0+0)*UU + t] = a0;
    g_dec_proj[(b0+1)*UU + t] = a1;
    g_dec_proj[(b0+2)*UU + t] = a2;
    g_dec_proj[(b0+3)*UU + t] = a3;
}

// ---------------------------------------------------------------------------
// K2: fused split-bf16 score GEMM (mma.sync + ldmatrix) + tanh/V epilogue.
//   C[M, U] = enc*W1 via 3 split terms: Ahi*Bhi + Ahi*Blo + Alo*Bhi.
//   CTA: 128 (m) x 256 (n), 512 threads. K-chunk 64, term-INNER loop:
//   per chunk, A fp32 is loaded once and split in-kernel (no prep pass).
//   2-stage pipeline: per stage Ahi 16K + Alo 16K + Bhi 32K + Blo 32K = 96KB.
// ---------------------------------------------------------------------------
#define STAGE 98304
#define SMEM_DYN (2*STAGE)   // 192KB

__global__ __launch_bounds__(512, 1) void score_kernel(const float* __restrict__ enc,
                                                       const float* __restrict__ Vw) {
    extern __shared__ char dsm[];
    __shared__ float dp_s[256];
    __shared__ float vw_s[256];
    __shared__ float s_red[4][128];

    const uint32_t sb = smem_u32(dsm);
    const int tid  = threadIdx.x;
    const int wid  = tid >> 5;
    const int lane = tid & 31;
    const int mtile = blockIdx.x >> 1;
    const int nt    = blockIdx.x & 1;
    const int row0  = mtile * 128;
    const int b     = mtile / 6;          // 6 m-tiles per batch
    const int m0 = (wid >> 2) * 32;       // warp m-offset
    const int n0 = (wid & 3) * 64;        // warp n-offset
    const int rl = lane >> 2;             // fragment row group 0..7
    const int qt = lane & 3;              // fragment col group

    // ldmatrix lane addressing constants
    const int sub = lane >> 3, i8 = lane & 7;
    const uint32_t x8   = (uint32_t)i8;
    const uint32_t aRow = (uint32_t)(m0 + ((sub & 1) << 3) + i8) * 128;
    const uint32_t aCS  = (uint32_t)(sub >> 1);
    const uint32_t bRow = (uint32_t)(n0 + ((sub >> 1) << 3) + i8) * 128;
    const uint32_t bCS  = (uint32_t)(sub & 1);

    if (tid < 256) {
        dp_s[tid] = g_dec_proj[b*UU + nt*256 + tid];
        vw_s[tid] = Vw[nt*256 + tid];
    }

    float acc[2][8][4];
    #pragma unroll
    for (int mi = 0; mi < 2; mi++)
        #pragma unroll
        for (int j = 0; j < 8; j++)
            #pragma unroll
            for (int c = 0; c < 4; c++) acc[mi][j][c] = 0.f;

    const __nv_bfloat16* __restrict__ Bhi = g_W1T_hi + (size_t)(nt*256)*DD;
    const __nv_bfloat16* __restrict__ Blo = g_W1T_lo + (size_t)(nt*256)*DD;

    // ---- producers ----
    auto produceB = [&](int kt, int s) {
        const uint32_t bh = sb + (uint32_t)s*STAGE + 32768;
        const uint32_t bl = bh + 32768;
        const __nv_bfloat16* sh = Bhi + kt*64;
        const __nv_bfloat16* sl = Blo + kt*64;
        #pragma unroll
        for (int i = 0; i < 4; i++) {
            int id = tid + i*512;              // 0..2047
            int r = id >> 3, j = id & 7;
            uint32_t off = (uint32_t)r*128 + (uint32_t)((j ^ (r & 7)) << 4);
            cp16(bh + off, sh + (size_t)r*DD + j*8);
            cp16(bl + off, sl + (size_t)r*DD + j*8);
        }
    };
    auto produceA = [&](int kt, int s) {
        char* ah = dsm + (size_t)s*STAGE;
        char* al = ah + 16384;
        const float* src = enc + (size_t)row0*DD + kt*64;
        #pragma unroll
        for (int i = 0; i < 4; i++) {
            int id = tid + i*512;              // 0..2047 float4s
            int r = id >> 4, jc = id & 15;
            float4 v = *(const float4*)(src + (size_t)r*DD + jc*4);
            __nv_bfloat162 h01 = __floats2bfloat162_rn(v.x, v.y);
            __nv_bfloat162 h23 = __floats2bfloat162_rn(v.z, v.w);
            __nv_bfloat162 l01 = __floats2bfloat162_rn(v.x - __low2float(h01),
                                                       v.y - __high2float(h01));
            __nv_bfloat162 l23 = __floats2bfloat162_rn(v.z - __low2float(h23),
                                                       v.w - __high2float(h23));
            uint32_t off = (uint32_t)r*128 +
                           (uint32_t)((((jc >> 1) ^ (r & 7)) << 4) | ((jc & 1) * 8));
            *(uint2*)(ah + off) = make_uint2(reinterpret_cast<uint32_t&>(h01),
                                             reinterpret_cast<uint32_t&>(h23));
            *(uint2*)(al + off) = make_uint2(reinterpret_cast<uint32_t&>(l01),
                                             reinterpret_cast<uint32_t&>(l23));
        }
    };

    // ---- prologue ----
    produceB(0, 0); cp_commit(); produceA(0, 0);
    produceB(1, 1); cp_commit(); produceA(1, 1);
    CP_WAIT(1);
    __syncthreads();

    // ---- mainloop: 8 chunks x 3 terms x 4 k16-steps ----
    #pragma unroll 1
    for (int kt = 0; kt < 8; kt++) {
        const uint32_t st = sb + (uint32_t)(kt & 1)*STAGE;
        #pragma unroll
        for (int term = 0; term < 3; term++) {
            const uint32_t stA = st + ((term == 2) ? 16384u : 0u);
            const uint32_t stB = st + 32768u + ((term == 1) ? 32768u : 0u);
            #pragma unroll
            for (int ks = 0; ks < 4; ks++) {
                uint32_t a0[4], a1[4];
                uint32_t achunk = (((uint32_t)(2*ks) + aCS) ^ x8) << 4;
                ldsm4(a0, stA + aRow + achunk);
                ldsm4(a1, stA + aRow + 2048 + achunk);
                uint32_t bchunk = (((uint32_t)(2*ks) + bCS) ^ x8) << 4;
                #pragma unroll
                for (int jp = 0; jp < 4; jp++) {
                    uint32_t bq[4];
                    ldsm4(bq, stB + bRow + (uint32_t)jp*2048 + bchunk);
                    mma_bf16(acc[0][2*jp],   a0, bq[0], bq[1]);
                    mma_bf16(acc[1][2*jp],   a1, bq[0], bq[1]);
                    mma_bf16(acc[0][2*jp+1], a0, bq[2], bq[3]);
                    mma_bf16(acc[1][2*jp+1], a1, bq[2], bq[3]);
                }
            }
        }
        __syncthreads();                       // all reads of stage kt&1 done
        if (kt + 2 < 8) {
            produceB(kt + 2, kt & 1); cp_commit();
            produceA(kt + 2, kt & 1);
        }
        if (kt + 1 < 8) {
            if (kt + 2 < 8) { CP_WAIT(1); } else { CP_WAIT(0); }
            __syncthreads();                   // stage (kt+1)&1 ready for all
        }
    }

    // ---- epilogue: tanh + V-dot ----
    float p[4] = {0.f, 0.f, 0.f, 0.f};
    #pragma unroll
    for (int mi = 0; mi < 2; mi++)
        #pragma unroll
        for (int j = 0; j < 8; j++)
            #pragma unroll
            for (int cc = 0; cc < 4; cc++) {
                int u = n0 + j*8 + qt*2 + (cc & 1);
                int h = cc >> 1;
                p[mi*2 + h] += tanhf(acc[mi][j][cc] + dp_s[u]) * vw_s[u];
            }
    #pragma unroll
    for (int i = 0; i < 4; i++) {
        p[i] += __shfl_xor_sync(0xFFFFFFFF, p[i], 1);
        p[i] += __shfl_xor_sync(0xFFFFFFFF, p[i], 2);
    }
    if (qt == 0) {
        #pragma unroll
        for (int mi = 0; mi < 2; mi++)
            #pragma unroll
            for (int h = 0; h < 2; h++)
                s_red[wid & 3][m0 + mi*16 + h*8 + rl] = p[mi*2 + h];
    }
    __syncthreads();
    if (tid < 128)
        g_part[nt*MM + row0 + tid] =
            (s_red[0][tid] + s_red[1][tid]) + (s_red[2][tid] + s_red[3][tid]);
}

// ---------------------------------------------------------------------------
// K3: softmax over H (axis=1) per (b,w). V_b omitted (shift-invariant).
// ---------------------------------------------------------------------------
__global__ void softmax_kernel(float* __restrict__ attn) {
    int idx = blockIdx.x * blockDim.x + threadIdx.x;
    if (idx >= BB*WW) return;
    int b = idx / WW, w = idx - b*WW;
    const float* p0 = g_part + b*HW + w;
    const float* p1 = g_part + MM + b*HW + w;
    float sc[HH];
    float mx = -1e30f;
    #pragma unroll
    for (int h = 0; h < HH; h++) {
        sc[h] = p0[h*WW] + p1[h*WW];
        mx = fmaxf(mx, sc[h]);
    }
    float sum = 0.f;
    #pragma unroll
    for (int h = 0; h < HH; h++) { sc[h] = __expf(sc[h] - mx); sum += sc[h]; }
    float inv = 1.0f / sum;
    #pragma unroll
    for (int h = 0; h < HH; h++)
        attn[b*HW + h*WW + w] = sc[h] * inv;
}

// ---------------------------------------------------------------------------
// K4: context partials. grid(128,4): block (b,q) sums 192 hw rows.
// ---------------------------------------------------------------------------
__global__ __launch_bounds__(128) void context_kernel(const float* __restrict__ enc,
                                                      const float* __restrict__ attn) {
    __shared__ float s_a[192];
    int b = blockIdx.x, q = blockIdx.y;
    int t = threadIdx.x;                       // owns d = 4t..4t+3
    int base = q * 192;
    for (int i = t; i < 192; i += 128) s_a[i] = attn[b*HW + base + i];
    __syncthreads();
    const float4* __restrict__ e =
        (const float4*)(enc + ((size_t)b*HW + base)*DD) + t;
    float4 a0 = {0,0,0,0}, a1 = a0, a2 = a0, a3 = a0;
    #pragma unroll 4
    for (int i = 0; i < 192; i += 4) {
        float w0 = s_a[i], w1 = s_a[i+1], w2 = s_a[i+2], w3 = s_a[i+3];
        float4 e0 = e[(size_t)(i+0)*128];
        float4 e1 = e[(size_t)(i+1)*128];
        float4 e2 = e[(size_t)(i+2)*128];
        float4 e3 = e[(size_t)(i+3)*128];
        a0.x += w0*e0.x; a0.y += w0*e0.y; a0.z += w0*e0.z; a0.w += w0*e0.w;
        a1.x += w1*e1.x; a1.y += w1*e1.y; a1.z += w1*e1.z; a1.w += w1*e1.w;
        a2.x += w2*e2.x; a2.y += w2*e2.y; a2.z += w2*e2.z; a2.w += w2*e2.w;
        a3.x += w3*e3.x; a3.y += w3*e3.y; a3.z += w3*e3.z; a3.w += w3*e3.w;
    }
    float4 r;
    r.x = (a0.x + a1.x) + (a2.x + a3.x);
    r.y = (a0.y + a1.y) + (a2.y + a3.y);
    r.z = (a0.z + a1.z) + (a2.z + a3.z);
    r.w = (a0.w + a1.w) + (a2.w + a3.w);
    ((float4*)(g_ctx_part + ((size_t)q*BB + b)*DD))[t] = r;
}

__global__ void ctx_reduce_kernel(float* __restrict__ ctx) {
    int i = blockIdx.x * 256 + threadIdx.x;    // 0..16383 float4s
    const float4* p = (const float4*)g_ctx_part;
    float4 a = p[i], b = p[i + 16384], c = p[i + 32768], d = p[i + 49152];
    float4 r;
    r.x = (a.x + b.x) + (c.x + d.x);
    r.y = (a.y + b.y) + (c.y + d.y);
    r.z = (a.z + b.z) + (c.z + d.z);
    r.w = (a.w + b.w) + (c.w + d.w);
    ((float4*)ctx)[i] = r;
}

// ---------------------------------------------------------------------------
extern "C" void kernel_launch(void* const* d_in, const int* in_sizes, int n_in,
                              void* d_out, int out_size) {
    const float* dec  = (const float*)d_in[0];   // (128, 512)
    const float* enc  = (const float*)d_in[1];   // (128, 16, 48, 512)
    const float* W1w  = (const float*)d_in[2];   // (512, 512)
    const float* W1b  = (const float*)d_in[3];
    const float* W2w  = (const float*)d_in[4];
    const float* W2b  = (const float*)d_in[5];
    const float* Vw   = (const float*)d_in[6];   // (512, 1)
    // V_b unused: cancels in softmax.

    float* ctx_out  = (float*)d_out;             // (128, 512)
    float* attn_out = (float*)d_out + BB*DD;     // (128, 16, 48, 1)

    static bool attr_set = false;
    if (!attr_set) {
        cudaFuncSetAttribute(score_kernel,
                             cudaFuncAttributeMaxDynamicSharedMemorySize, SMEM_DYN);
        attr_set = true;
    }

    prep_w1_kernel<<<1024, 256>>>(W1w);
    dec_proj_kernel<<<BB/4, 512>>>(dec, W2w, W1b, W2b);
    score_kernel<<<(MM/128)*2, 512, SMEM_DYN>>>(enc, Vw);
    softmax_kernel<<<(BB*WW + 127)/128, 128>>>(attn_out);
    context_kernel<<<dim3(BB, 4), 128>>>(enc, attn_out);
    ctx_reduce_kernel<<<64, 256>>>(ctx_out);
}

// round 5
// speedup vs baseline: 1.0523x; 1.0523x over previous
#include <cuda_runtime.h>
#include <cuda_bf16.h>
#include <cstdint>
#include <math.h>

// Problem constants
#define BB 128
#define HH 16
#define WW 48
#define DD 512
#define UU 512
#define HW (HH*WW)          // 768
#define MM (BB*HW)          // 98304

// ---------------------------------------------------------------------------
// Device globals (scratch; no allocation allowed)
// ---------------------------------------------------------------------------
__device__ float         g_dec_proj[BB*UU];       // dec @ W2 + b1 + b2
__device__ float         g_part[2*MM];            // partial scores per N-half
__device__ float         g_ctx_part[4*BB*DD];     // context partials
__device__ __nv_bfloat16 g_W1T_hi[UU*DD];         // W1^T split-hi [u][k]
__device__ __nv_bfloat16 g_W1T_lo[UU*DD];         // W1^T split-lo [u][k]
__device__ __nv_bfloat16 g_enc_hi[(size_t)MM*DD]; // enc split-hi  [m][k]
__device__ __nv_bfloat16 g_enc_lo[(size_t)MM*DD]; // enc split-lo  [m][k]

// ---------------------------------------------------------------------------
// Helpers
// ---------------------------------------------------------------------------
__device__ __forceinline__ uint32_t smem_u32(const void* p) {
    uint32_t a;
    asm("{ .reg .u64 t; cvta.to.shared.u64 t, %1; cvt.u32.u64 %0, t; }"
        : "=r"(a) : "l"(p));
    return a;
}

__device__ __forceinline__ void cp16(uint32_t s, const void* g) {
    asm volatile("cp.async.cg.shared.global [%0], [%1], 16;"
                 :: "r"(s), "l"(g) : "memory");
}
__device__ __forceinline__ void cp_commit() {
    asm volatile("cp.async.commit_group;" ::: "memory");
}
#define CP_WAIT(n) asm volatile("cp.async.wait_group %0;" :: "n"(n) : "memory")

__device__ __forceinline__ void ldsm4(uint32_t* r, uint32_t addr) {
    asm volatile("ldmatrix.sync.aligned.m8n8.x4.shared.b16 {%0,%1,%2,%3}, [%4];"
                 : "=r"(r[0]), "=r"(r[1]), "=r"(r[2]), "=r"(r[3]) : "r"(addr));
}

__device__ __forceinline__ void mma_bf16(float* c, const uint32_t* a,
                                         uint32_t b0, uint32_t b1) {
    asm volatile("mma.sync.aligned.m16n8k16.row.col.f32.bf16.bf16.f32 "
                 "{%0,%1,%2,%3}, {%4,%5,%6,%7}, {%8,%9}, {%0,%1,%2,%3};"
                 : "+f"(c[0]), "+f"(c[1]), "+f"(c[2]), "+f"(c[3])
                 : "r"(a[0]), "r"(a[1]), "r"(a[2]), "r"(a[3]),
                   "r"(b0), "r"(b1));
}

// ---------------------------------------------------------------------------
// K0a: W1 -> transposed bf16 hi/lo splits
// ---------------------------------------------------------------------------
__global__ void prep_w1_kernel(const float* __restrict__ W1) {
    int idx = blockIdx.x * 256 + threadIdx.x;    // 0..262143
    int k = idx >> 9, u = idx & 511;
    float x = W1[idx];
    __nv_bfloat16 h = __float2bfloat16(x);
    g_W1T_hi[u*DD + k] = h;
    g_W1T_lo[u*DD + k] = __float2bfloat16(x - __bfloat162float(h));
}

// ---------------------------------------------------------------------------
// K0b: enc fp32 -> bf16 hi/lo splits (4 elems/thread)
// ---------------------------------------------------------------------------
__global__ __launch_bounds__(256) void prep_enc_kernel(const float* __restrict__ enc) {
    size_t i4 = (size_t)blockIdx.x * 256 + threadIdx.x;  // float4 index
    float4 v = ((const float4*)enc)[i4];
    __nv_bfloat162 h01 = __floats2bfloat162_rn(v.x, v.y);
    __nv_bfloat162 h23 = __floats2bfloat162_rn(v.z, v.w);
    __nv_bfloat162 l01 = __floats2bfloat162_rn(v.x - __low2float(h01),
                                               v.y - __high2float(h01));
    __nv_bfloat162 l23 = __floats2bfloat162_rn(v.z - __low2float(h23),
                                               v.w - __high2float(h23));
    ((uint2*)g_enc_hi)[i4] = make_uint2(reinterpret_cast<uint32_t&>(h01),
                                        reinterpret_cast<uint32_t&>(h23));
    ((uint2*)g_enc_lo)[i4] = make_uint2(reinterpret_cast<uint32_t&>(l01),
                                        reinterpret_cast<uint32_t&>(l23));
}

// ---------------------------------------------------------------------------
// K1: dec_proj[b,u] = sum_d dec[b,d]*W2[d,u] + W1_b[u] + W2_b[u]
// grid 32 (4 batches each), block 512.
// ---------------------------------------------------------------------------
__global__ __launch_bounds__(512) void dec_proj_kernel(const float* __restrict__ dec,
                                                       const float* __restrict__ W2,
                                                       const float* __restrict__ b1,
                                                       const float* __restrict__ b2) {
    __shared__ float s_dec[4][DD];
    int b0 = blockIdx.x * 4;
    int t = threadIdx.x;
    #pragma unroll
    for (int i = 0; i < 4; i++) s_dec[i][t] = dec[(b0 + i)*DD + t];
    __syncthreads();
    float bias = b1[t] + b2[t];
    float a0 = bias, a1 = bias, a2 = bias, a3 = bias;
    #pragma unroll 8
    for (int d = 0; d < DD; d++) {
        float w = W2[(size_t)d*UU + t];
        a0 += s_dec[0][d] * w;
        a1 += s_dec[1][d] * w;
        a2 += s_dec[2][d] * w;
        a3 += s_dec[3][d] * w;
    }
    g_dec_proj[(b0+0)*UU + t] = a0;
    g_dec_proj[(b0+1)*UU + t] = a1;
    g_dec_proj[(b0+2)*UU + t] = a2;
    g_dec_proj[(b0+3)*UU + t] = a3;
}

// ---------------------------------------------------------------------------
// K2: split-bf16 score GEMM (mma.sync + ldmatrix, all-cp.async) + epilogue.
//   C[M, U] = enc*W1 via Ahi*Bhi + Ahi*Blo + Alo*Bhi (term-inner).
//   CTA: 128 (m) x 256 (n), 512 threads, K-chunk 64.
//   Stage = Ahi 16K + Alo 16K + Bhi 32K + Blo 32K = 96KB; 2 stages.
// ---------------------------------------------------------------------------
#define STAGE 98304
#define SMEM_DYN (2*STAGE)   // 192KB

__global__ __launch_bounds__(512, 1) void score_kernel(const float* __restrict__ Vw) {
    extern __shared__ char dsm[];
    __shared__ float dp_s[256];
    __shared__ float vw_s[256];
    __shared__ float s_red[4][128];

    const uint32_t sb = smem_u32(dsm);
    const int tid  = threadIdx.x;
    const int wid  = tid >> 5;
    const int lane = tid & 31;
    const int mtile = blockIdx.x >> 1;
    const int nt    = blockIdx.x & 1;
    const int row0  = mtile * 128;
    const int b     = mtile / 6;          // 6 m-tiles per batch
    const int m0 = (wid >> 2) * 32;       // warp m-offset
    const int n0 = (wid & 3) * 64;        // warp n-offset
    const int rl = lane >> 2;             // fragment row group 0..7
    const int qt = lane & 3;              // fragment col group

    // ldmatrix lane addressing constants (validated in round 4)
    const int sub = lane >> 3, i8 = lane & 7;
    const uint32_t x8   = (uint32_t)i8;
    const uint32_t aRow = (uint32_t)(m0 + ((sub & 1) << 3) + i8) * 128;
    const uint32_t aCS  = (uint32_t)(sub >> 1);
    const uint32_t bRow = (uint32_t)(n0 + ((sub >> 1) << 3) + i8) * 128;
    const uint32_t bCS  = (uint32_t)(sub & 1);

    if (tid < 256) {
        dp_s[tid] = g_dec_proj[b*UU + nt*256 + tid];
        vw_s[tid] = Vw[nt*256 + tid];
    }

    float acc[2][8][4];
    #pragma unroll
    for (int mi = 0; mi < 2; mi++)
        #pragma unroll
        for (int j = 0; j < 8; j++)
            #pragma unroll
            for (int c = 0; c < 4; c++) acc[mi][j][c] = 0.f;

    const __nv_bfloat16* __restrict__ Ahi = g_enc_hi + (size_t)row0*DD;
    const __nv_bfloat16* __restrict__ Alo = g_enc_lo + (size_t)row0*DD;
    const __nv_bfloat16* __restrict__ Bhi = g_W1T_hi + (size_t)(nt*256)*DD;
    const __nv_bfloat16* __restrict__ Blo = g_W1T_lo + (size_t)(nt*256)*DD;

    // ---- producer: one K=64 chunk (A hi/lo + B hi/lo), all cp.async ----
    auto produce = [&](int kt, int s) {
        const uint32_t ah = sb + (uint32_t)s*STAGE;
        const uint32_t al = ah + 16384;
        const uint32_t bh = ah + 32768;
        const uint32_t bl = bh + 32768;
        const int kk = kt * 64;
        #pragma unroll
        for (int i = 0; i < 2; i++) {          // A: 1024 x 16B per half
            int id = tid + i*512;
            int r = id >> 3, j = id & 7;
            uint32_t off = (uint32_t)r*128 + (uint32_t)((j ^ (r & 7)) << 4);
            cp16(ah + off, Ahi + (size_t)r*DD + kk + j*8);
            cp16(al + off, Alo + (size_t)r*DD + kk + j*8);
        }
        #pragma unroll
        for (int i = 0; i < 4; i++) {          // B: 2048 x 16B per half
            int id = tid + i*512;
            int r = id >> 3, j = id & 7;
            uint32_t off = (uint32_t)r*128 + (uint32_t)((j ^ (r & 7)) << 4);
            cp16(bh + off, Bhi + (size_t)r*DD + kk + j*8);
            cp16(bl + off, Blo + (size_t)r*DD + kk + j*8);
        }
        cp_commit();
    };

    // ---- prologue ----
    produce(0, 0);
    produce(1, 1);
    CP_WAIT(1);
    __syncthreads();

    // ---- mainloop: 8 chunks x 3 terms x 4 k16-steps ----
    #pragma unroll 1
    for (int kt = 0; kt < 8; kt++) {
        const uint32_t st = sb + (uint32_t)(kt & 1)*STAGE;
        #pragma unroll
        for (int term = 0; term < 3; term++) {
            const uint32_t stA = st + ((term == 2) ? 16384u : 0u);
            const uint32_t stB = st + 32768u + ((term == 1) ? 32768u : 0u);
            #pragma unroll
            for (int ks = 0; ks < 4; ks++) {
                uint32_t a0[4], a1[4];
                uint32_t achunk = (((uint32_t)(2*ks) + aCS) ^ x8) << 4;
                ldsm4(a0, stA + aRow + achunk);
                ldsm4(a1, stA + aRow + 2048 + achunk);
                uint32_t bchunk = (((uint32_t)(2*ks) + bCS) ^ x8) << 4;
                #pragma unroll
                for (int jp = 0; jp < 4; jp++) {
                    uint32_t bq[4];
                    ldsm4(bq, stB + bRow + (uint32_t)jp*2048 + bchunk);
                    mma_bf16(acc[0][2*jp],   a0, bq[0], bq[1]);
                    mma_bf16(acc[1][2*jp],   a1, bq[0], bq[1]);
                    mma_bf16(acc[0][2*jp+1], a0, bq[2], bq[3]);
                    mma_bf16(acc[1][2*jp+1], a1, bq[2], bq[3]);
                }
            }
        }
        __syncthreads();                       // all reads of stage kt&1 done
        if (kt + 2 < 8) produce(kt + 2, kt & 1);
        if (kt + 1 < 8) {
            if (kt + 2 < 8) { CP_WAIT(1); } else { CP_WAIT(0); }
            __syncthreads();                   // stage (kt+1)&1 ready for all
        }
    }

    // ---- epilogue: tanh + V-dot ----
    float p[4] = {0.f, 0.f, 0.f, 0.f};
    #pragma unroll
    for (int mi = 0; mi < 2; mi++)
        #pragma unroll
        for (int j = 0; j < 8; j++)
            #pragma unroll
            for (int cc = 0; cc < 4; cc++) {
                int u = n0 + j*8 + qt*2 + (cc & 1);
                int h = cc >> 1;
                p[mi*2 + h] += tanhf(acc[mi][j][cc] + dp_s[u]) * vw_s[u];
            }
    #pragma unroll
    for (int i = 0; i < 4; i++) {
        p[i] += __shfl_xor_sync(0xFFFFFFFF, p[i], 1);
        p[i] += __shfl_xor_sync(0xFFFFFFFF, p[i], 2);
    }
    if (qt == 0) {
        #pragma unroll
        for (int mi = 0; mi < 2; mi++)
            #pragma unroll
            for (int h = 0; h < 2; h++)
                s_red[wid & 3][m0 + mi*16 + h*8 + rl] = p[mi*2 + h];
    }
    __syncthreads();
    if (tid < 128)
        g_part[nt*MM + row0 + tid] =
            (s_red[0][tid] + s_red[1][tid]) + (s_red[2][tid] + s_red[3][tid]);
}

// ---------------------------------------------------------------------------
// K3: softmax over H (axis=1) per (b,w). V_b omitted (shift-invariant).
// ---------------------------------------------------------------------------
__global__ void softmax_kernel(float* __restrict__ attn) {
    int idx = blockIdx.x * blockDim.x + threadIdx.x;
    if (idx >= BB*WW) return;
    int b = idx / WW, w = idx - b*WW;
    const float* p0 = g_part + b*HW + w;
    const float* p1 = g_part + MM + b*HW + w;
    float sc[HH];
    float mx = -1e30f;
    #pragma unroll
    for (int h = 0; h < HH; h++) {
        sc[h] = p0[h*WW] + p1[h*WW];
        mx = fmaxf(mx, sc[h]);
    }
    float sum = 0.f;
    #pragma unroll
    for (int h = 0; h < HH; h++) { sc[h] = __expf(sc[h] - mx); sum += sc[h]; }
    float inv = 1.0f / sum;
    #pragma unroll
    for (int h = 0; h < HH; h++)
        attn[b*HW + h*WW + w] = sc[h] * inv;
}

// ---------------------------------------------------------------------------
// K4: context partials. grid(128,4): block (b,q) sums 192 hw rows.
// ---------------------------------------------------------------------------
__global__ __launch_bounds__(128) void context_kernel(const float* __restrict__ enc,
                                                      const float* __restrict__ attn) {
    __shared__ float s_a[192];
    int b = blockIdx.x, q = blockIdx.y;
    int t = threadIdx.x;                       // owns d = 4t..4t+3
    int base = q * 192;
    for (int i = t; i < 192; i += 128) s_a[i] = attn[b*HW + base + i];
    __syncthreads();
    const float4* __restrict__ e =
        (const float4*)(enc + ((size_t)b*HW + base)*DD) + t;
    float4 a0 = {0,0,0,0}, a1 = a0, a2 = a0, a3 = a0;
    #pragma unroll 4
    for (int i = 0; i < 192; i += 4) {
        float w0 = s_a[i], w1 = s_a[i+1], w2 = s_a[i+2], w3 = s_a[i+3];
        float4 e0 = e[(size_t)(i+0)*128];
        float4 e1 = e[(size_t)(i+1)*128];
        float4 e2 = e[(size_t)(i+2)*128];
        float4 e3 = e[(size_t)(i+3)*128];
        a0.x += w0*e0.x; a0.y += w0*e0.y; a0.z += w0*e0.z; a0.w += w0*e0.w;
        a1.x += w1*e1.x; a1.y += w1*e1.y; a1.z += w1*e1.z; a1.w += w1*e1.w;
        a2.x += w2*e2.x; a2.y += w2*e2.y; a2.z += w2*e2.z; a2.w += w2*e2.w;
        a3.x += w3*e3.x; a3.y += w3*e3.y; a3.z += w3*e3.z; a3.w += w3*e3.w;
    }
    float4 r;
    r.x = (a0.x + a1.x) + (a2.x + a3.x);
    r.y = (a0.y + a1.y) + (a2.y + a3.y);
    r.z = (a0.z + a1.z) + (a2.z + a3.z);
    r.w = (a0.w + a1.w) + (a2.w + a3.w);
    ((float4*)(g_ctx_part + ((size_t)q*BB + b)*DD))[t] = r;
}

__global__ void ctx_reduce_kernel(float* __restrict__ ctx) {
    int i = blockIdx.x * 256 + threadIdx.x;    // 0..16383 float4s
    const float4* p = (const float4*)g_ctx_part;
    float4 a = p[i], b = p[i + 16384], c = p[i + 32768], d = p[i + 49152];
    float4 r;
    r.x = (a.x + b.x) + (c.x + d.x);
    r.y = (a.y + b.y) + (c.y + d.y);
    r.z = (a.z + b.z) + (c.z + d.z);
    r.w = (a.w + b.w) + (c.w + d.w);
    ((float4*)ctx)[i] = r;
}

// ---------------------------------------------------------------------------
extern "C" void kernel_launch(void* const* d_in, const int* in_sizes, int n_in,
                              void* d_out, int out_size) {
    const float* dec  = (const float*)d_in[0];   // (128, 512)
    const float* enc  = (const float*)d_in[1];   // (128, 16, 48, 512)
    const float* W1w  = (const float*)d_in[2];   // (512, 512)
    const float* W1b  = (const float*)d_in[3];
    const float* W2w  = (const float*)d_in[4];
    const float* W2b  = (const float*)d_in[5];
    const float* Vw   = (const float*)d_in[6];   // (512, 1)
    // V_b unused: cancels in softmax.

    float* ctx_out  = (float*)d_out;             // (128, 512)
    float* attn_out = (float*)d_out + BB*DD;     // (128, 16, 48, 1)

    static bool attr_set = false;
    if (!attr_set) {
        cudaFuncSetAttribute(score_kernel,
                             cudaFuncAttributeMaxDynamicSharedMemorySize, SMEM_DYN);
        attr_set = true;
    }

    prep_w1_kernel<<<1024, 256>>>(W1w);
    prep_enc_kernel<<<(int)((size_t)MM*DD/4/256), 256>>>(enc);
    dec_proj_kernel<<<BB/4, 512>>>(dec, W2w, W1b, W2b);
    score_kernel<<<(MM/128)*2, 512, SMEM_DYN>>>(Vw);
    softmax_kernel<<<(BB*WW + 127)/128, 128>>>(attn_out);
    context_kernel<<<dim3(BB, 4), 128>>>(enc, attn_out);
    ctx_reduce_kernel<<<64, 256>>>(ctx_out);
}

// round 6
// speedup vs baseline: 1.6248x; 1.5439x over previous
#include <cuda_runtime.h>
#include <cuda_fp16.h>
#include <cstdint>
#include <math.h>

// Problem constants
#define BB 128
#define HH 16
#define WW 48
#define DD 512
#define UU 512
#define HW (HH*WW)          // 768
#define MM (BB*HW)          // 98304

// ---------------------------------------------------------------------------
// Device globals (scratch; no allocation allowed)
// ---------------------------------------------------------------------------
__device__ float  g_dec_proj[BB*UU];          // dec @ W2 + b1 + b2
__device__ float  g_part[2*MM];               // partial scores per N-half
__device__ float  g_ctx_part[4*BB*DD];        // context partials
__device__ __half g_W1T[UU*DD];               // W1^T fp16 [u][k]
__device__ __half g_enc_hi[(size_t)MM*DD];    // enc fp16 split-hi [m][k]
__device__ __half g_enc_lo[(size_t)MM*DD];    // enc fp16 split-lo [m][k]

// ---------------------------------------------------------------------------
// Helpers
// ---------------------------------------------------------------------------
__device__ __forceinline__ uint32_t smem_u32(const void* p) {
    uint32_t a;
    asm("{ .reg .u64 t; cvta.to.shared.u64 t, %1; cvt.u32.u64 %0, t; }"
        : "=r"(a) : "l"(p));
    return a;
}

__device__ __forceinline__ void cp16(uint32_t s, const void* g) {
    asm volatile("cp.async.cg.shared.global [%0], [%1], 16;"
                 :: "r"(s), "l"(g) : "memory");
}
__device__ __forceinline__ void cp_commit() {
    asm volatile("cp.async.commit_group;" ::: "memory");
}
#define CP_WAIT(n) asm volatile("cp.async.wait_group %0;" :: "n"(n) : "memory")

__device__ __forceinline__ void ldsm4(uint32_t* r, uint32_t addr) {
    asm volatile("ldmatrix.sync.aligned.m8n8.x4.shared.b16 {%0,%1,%2,%3}, [%4];"
                 : "=r"(r[0]), "=r"(r[1]), "=r"(r[2]), "=r"(r[3]) : "r"(addr));
}

__device__ __forceinline__ void mma_f16(float* c, const uint32_t* a,
                                        uint32_t b0, uint32_t b1) {
    asm volatile("mma.sync.aligned.m16n8k16.row.col.f32.f16.f16.f32 "
                 "{%0,%1,%2,%3}, {%4,%5,%6,%7}, {%8,%9}, {%0,%1,%2,%3};"
                 : "+f"(c[0]), "+f"(c[1]), "+f"(c[2]), "+f"(c[3])
                 : "r"(a[0]), "r"(a[1]), "r"(a[2]), "r"(a[3]),
                   "r"(b0), "r"(b1));
}

// ---------------------------------------------------------------------------
// K0a: W1 -> transposed fp16  (g_W1T[u][k] = fp16(W1[k][u]))
// ---------------------------------------------------------------------------
__global__ void prep_w1_kernel(const float* __restrict__ W1) {
    int idx = blockIdx.x * 256 + threadIdx.x;    // 0..262143
    int k = idx >> 9, u = idx & 511;
    g_W1T[u*DD + k] = __float2half_rn(W1[idx]);
}

// ---------------------------------------------------------------------------
// K0b: enc fp32 -> fp16 hi/lo splits (4 elems/thread)
// ---------------------------------------------------------------------------
__global__ __launch_bounds__(256) void prep_enc_kernel(const float* __restrict__ enc) {
    size_t i4 = (size_t)blockIdx.x * 256 + threadIdx.x;  // float4 index
    float4 v = ((const float4*)enc)[i4];
    __half2 h01 = __floats2half2_rn(v.x, v.y);
    __half2 h23 = __floats2half2_rn(v.z, v.w);
    __half2 l01 = __floats2half2_rn(v.x - __half2float(__low2half(h01)),
                                    v.y - __half2float(__high2half(h01)));
    __half2 l23 = __floats2half2_rn(v.z - __half2float(__low2half(h23)),
                                    v.w - __half2float(__high2half(h23)));
    ((uint2*)g_enc_hi)[i4] = make_uint2(reinterpret_cast<uint32_t&>(h01),
                                        reinterpret_cast<uint32_t&>(h23));
    ((uint2*)g_enc_lo)[i4] = make_uint2(reinterpret_cast<uint32_t&>(l01),
                                        reinterpret_cast<uint32_t&>(l23));
}

// ---------------------------------------------------------------------------
// K1: dec_proj[b,u] = sum_d dec[b,d]*W2[d,u] + W1_b[u] + W2_b[u]
// ---------------------------------------------------------------------------
__global__ __launch_bounds__(512) void dec_proj_kernel(const float* __restrict__ dec,
                                                       const float* __restrict__ W2,
                                                       const float* __restrict__ b1,
                                                       const float* __restrict__ b2) {
    __shared__ float s_dec[4][DD];
    int b0 = blockIdx.x * 4;
    int t = threadIdx.x;
    #pragma unroll
    for (int i = 0; i < 4; i++) s_dec[i][t] = dec[(b0 + i)*DD + t];
    __syncthreads();
    float bias = b1[t] + b2[t];
    float a0 = bias, a1 = bias, a2 = bias, a3 = bias;
    #pragma unroll 8
    for (int d = 0; d < DD; d++) {
        float w = W2[(size_t)d*UU + t];
        a0 += s_dec[0][d] * w;
        a1 += s_dec[1][d] * w;
        a2 += s_dec[2][d] * w;
        a3 += s_dec[3][d] * w;
    }
    g_dec_proj[(b0+0)*UU + t] = a0;
    g_dec_proj[(b0+1)*UU + t] = a1;
    g_dec_proj[(b0+2)*UU + t] = a2;
    g_dec_proj[(b0+3)*UU + t] = a3;
}

// ---------------------------------------------------------------------------
// K2: 2-term fp16 score GEMM (mma.sync + ldmatrix) + fused tanh/V epilogue.
//   C = enc*W1 = (Ahi + Alo) * W,  A split exact in fp16, W single fp16.
//   CTA: 128 (m) x 256 (n), 512 threads, K-chunk 64.
//   Stage = Ahi 16K + Alo 16K + W 32K = 64KB; 3 stages; 1 sync per chunk.
// ---------------------------------------------------------------------------
#define STAGE 65536
#define SMEM_DYN (3*STAGE)   // 192KB

__global__ __launch_bounds__(512, 1) void score_kernel(const float* __restrict__ Vw) {
    extern __shared__ char dsm[];
    __shared__ float dp_s[256];
    __shared__ float vw_s[256];
    __shared__ float s_red[4][128];

    const uint32_t sb = smem_u32(dsm);
    const int tid  = threadIdx.x;
    const int wid  = tid >> 5;
    const int lane = tid & 31;
    const int mtile = blockIdx.x >> 1;
    const int nt    = blockIdx.x & 1;
    const int row0  = mtile * 128;
    const int b     = mtile / 6;          // 6 m-tiles per batch
    const int m0 = (wid >> 2) * 32;       // warp m-offset
    const int n0 = (wid & 3) * 64;        // warp n-offset
    const int rl = lane >> 2;             // fragment row group 0..7
    const int qt = lane & 3;              // fragment col group

    // ldmatrix lane addressing constants (validated rounds 4-5)
    const int sub = lane >> 3, i8 = lane & 7;
    const uint32_t x8   = (uint32_t)i8;
    const uint32_t aRow = (uint32_t)(m0 + ((sub & 1) << 3) + i8) * 128;
    const uint32_t aCS  = (uint32_t)(sub >> 1);
    const uint32_t bRow = (uint32_t)(n0 + ((sub >> 1) << 3) + i8) * 128;
    const uint32_t bCS  = (uint32_t)(sub & 1);

    if (tid < 256) {
        dp_s[tid] = g_dec_proj[b*UU + nt*256 + tid];
        vw_s[tid] = Vw[nt*256 + tid];
    }

    float acc[2][8][4];
    #pragma unroll
    for (int mi = 0; mi < 2; mi++)
        #pragma unroll
        for (int j = 0; j < 8; j++)
            #pragma unroll
            for (int c = 0; c < 4; c++) acc[mi][j][c] = 0.f;

    const __half* __restrict__ Ahi = g_enc_hi + (size_t)row0*DD;
    const __half* __restrict__ Alo = g_enc_lo + (size_t)row0*DD;
    const __half* __restrict__ Wp  = g_W1T + (size_t)(nt*256)*DD;

    // ---- producer: one K=64 chunk (Ahi + Alo + W), all cp.async ----
    auto produce = [&](int kt) {
        const uint32_t ah = sb + (uint32_t)(kt % 3)*STAGE;
        const uint32_t al = ah + 16384;
        const uint32_t ws = ah + 32768;
        const int kk = kt * 64;
        #pragma unroll
        for (int i = 0; i < 2; i++) {          // A halves: 1024 x 16B each
            int id = tid + i*512;
            int r = id >> 3, j = id & 7;
            uint32_t off = (uint32_t)r*128 + (uint32_t)((j ^ (r & 7)) << 4);
            cp16(ah + off, Ahi + (size_t)r*DD + kk + j*8);
            cp16(al + off, Alo + (size_t)r*DD + kk + j*8);
        }
        #pragma unroll
        for (int i = 0; i < 4; i++) {          // W: 2048 x 16B
            int id = tid + i*512;
            int r = id >> 3, j = id & 7;
            uint32_t off = (uint32_t)r*128 + (uint32_t)((j ^ (r & 7)) << 4);
            cp16(ws + off, Wp + (size_t)r*DD + kk + j*8);
        }
        cp_commit();
    };

    // ---- prologue: fill 2 of 3 stages ----
    produce(0);
    produce(1);

    // ---- mainloop: 8 chunks, ONE sync per chunk ----
    #pragma unroll 1
    for (int kt = 0; kt < 8; kt++) {
        if (kt < 7) { CP_WAIT(1); } else { CP_WAIT(0); }
        __syncthreads();                   // chunk kt visible; all done with kt-1
        if (kt + 2 < 8) produce(kt + 2);   // overwrites stage consumed at kt-1

        const uint32_t st = sb + (uint32_t)(kt % 3)*STAGE;
        const uint32_t stW = st + 32768u;
        #pragma unroll
        for (int ks = 0; ks < 4; ks++) {
            uint32_t bq[4][4];
            uint32_t bchunk = (((uint32_t)(2*ks) + bCS) ^ x8) << 4;
            #pragma unroll
            for (int jp = 0; jp < 4; jp++)
                ldsm4(bq[jp], stW + bRow + (uint32_t)jp*2048 + bchunk);
            uint32_t achunk = (((uint32_t)(2*ks) + aCS) ^ x8) << 4;
            #pragma unroll
            for (int term = 0; term < 2; term++) {
                const uint32_t stA = st + (uint32_t)term*16384u;
                uint32_t a0[4], a1[4];
                ldsm4(a0, stA + aRow + achunk);
                ldsm4(a1, stA + aRow + 2048 + achunk);
                #pragma unroll
                for (int jp = 0; jp < 4; jp++) {
                    mma_f16(acc[0][2*jp],   a0, bq[jp][0], bq[jp][1]);
                    mma_f16(acc[1][2*jp],   a1, bq[jp][0], bq[jp][1]);
                    mma_f16(acc[0][2*jp+1], a0, bq[jp][2], bq[jp][3]);
                    mma_f16(acc[1][2*jp+1], a1, bq[jp][2], bq[jp][3]);
                }
            }
        }
    }

    // ---- epilogue: tanh + V-dot ----
    float p[4] = {0.f, 0.f, 0.f, 0.f};
    #pragma unroll
    for (int mi = 0; mi < 2; mi++)
        #pragma unroll
        for (int j = 0; j < 8; j++)
            #pragma unroll
            for (int cc = 0; cc < 4; cc++) {
                int u = n0 + j*8 + qt*2 + (cc & 1);
                int h = cc >> 1;
                p[mi*2 + h] += tanhf(acc[mi][j][cc] + dp_s[u]) * vw_s[u];
            }
    #pragma unroll
    for (int i = 0; i < 4; i++) {
        p[i] += __shfl_xor_sync(0xFFFFFFFF, p[i], 1);
        p[i] += __shfl_xor_sync(0xFFFFFFFF, p[i], 2);
    }
    if (qt == 0) {
        #pragma unroll
        for (int mi = 0; mi < 2; mi++)
            #pragma unroll
            for (int h = 0; h < 2; h++)
                s_red[wid & 3][m0 + mi*16 + h*8 + rl] = p[mi*2 + h];
    }
    __syncthreads();
    if (tid < 128)
        g_part[nt*MM + row0 + tid] =
            (s_red[0][tid] + s_red[1][tid]) + (s_red[2][tid] + s_red[3][tid]);
}

// ---------------------------------------------------------------------------
// K3: softmax over H (axis=1) per (b,w). V_b omitted (shift-invariant).
// ---------------------------------------------------------------------------
__global__ void softmax_kernel(float* __restrict__ attn) {
    int idx = blockIdx.x * blockDim.x + threadIdx.x;
    if (idx >= BB*WW) return;
    int b = idx / WW, w = idx - b*WW;
    const float* p0 = g_part + b*HW + w;
    const float* p1 = g_part + MM + b*HW + w;
    float sc[HH];
    float mx = -1e30f;
    #pragma unroll
    for (int h = 0; h < HH; h++) {
        sc[h] = p0[h*WW] + p1[h*WW];
        mx = fmaxf(mx, sc[h]);
    }
    float sum = 0.f;
    #pragma unroll
    for (int h = 0; h < HH; h++) { sc[h] = __expf(sc[h] - mx); sum += sc[h]; }
    float inv = 1.0f / sum;
    #pragma unroll
    for (int h = 0; h < HH; h++)
        attn[b*HW + h*WW + w] = sc[h] * inv;
}

// ---------------------------------------------------------------------------
// K4: context partials. grid(128,4): block (b,q) sums 192 hw rows.
// ---------------------------------------------------------------------------
__global__ __launch_bounds__(128) void context_kernel(const float* __restrict__ enc,
                                                      const float* __restrict__ attn) {
    __shared__ float s_a[192];
    int b = blockIdx.x, q = blockIdx.y;
    int t = threadIdx.x;                       // owns d = 4t..4t+3
    int base = q * 192;
    for (int i = t; i < 192; i += 128) s_a[i] = attn[b*HW + base + i];
    __syncthreads();
    const float4* __restrict__ e =
        (const float4*)(enc + ((size_t)b*HW + base)*DD) + t;
    float4 a0 = {0,0,0,0}, a1 = a0, a2 = a0, a3 = a0;
    #pragma unroll 4
    for (int i = 0; i < 192; i += 4) {
        float w0 = s_a[i], w1 = s_a[i+1], w2 = s_a[i+2], w3 = s_a[i+3];
        float4 e0 = e[(size_t)(i+0)*128];
        float4 e1 = e[(size_t)(i+1)*128];
        float4 e2 = e[(size_t)(i+2)*128];
        float4 e3 = e[(size_t)(i+3)*128];
        a0.x += w0*e0.x; a0.y += w0*e0.y; a0.z += w0*e0.z; a0.w += w0*e0.w;
        a1.x += w1*e1.x; a1.y += w1*e1.y; a1.z += w1*e1.z; a1.w += w1*e1.w;
        a2.x += w2*e2.x; a2.y += w2*e2.y; a2.z += w2*e2.z; a2.w += w2*e2.w;
        a3.x += w3*e3.x; a3.y += w3*e3.y; a3.z += w3*e3.z; a3.w += w3*e3.w;
    }
    float4 r;
    r.x = (a0.x + a1.x) + (a2.x + a3.x);
    r.y = (a0.y + a1.y) + (a2.y + a3.y);
    r.z = (a0.z + a1.z) + (a2.z + a3.z);
    r.w = (a0.w + a1.w) + (a2.w + a3.w);
    ((float4*)(g_ctx_part + ((size_t)q*BB + b)*DD))[t] = r;
}

__global__ void ctx_reduce_kernel(float* __restrict__ ctx) {
    int i = blockIdx.x * 256 + threadIdx.x;    // 0..16383 float4s
    const float4* p = (const float4*)g_ctx_part;
    float4 a = p[i], b = p[i + 16384], c = p[i + 32768], d = p[i + 49152];
    float4 r;
    r.x = (a.x + b.x) + (c.x + d.x);
    r.y = (a.y + b.y) + (c.y + d.y);
    r.z = (a.z + b.z) + (c.z + d.z);
    r.w = (a.w + b.w) + (c.w + d.w);
    ((float4*)ctx)[i] = r;
}

// ---------------------------------------------------------------------------
extern "C" void kernel_launch(void* const* d_in, const int* in_sizes, int n_in,
                              void* d_out, int out_size) {
    const float* dec  = (const float*)d_in[0];   // (128, 512)
    const float* enc  = (const float*)d_in[1];   // (128, 16, 48, 512)
    const float* W1w  = (const float*)d_in[2];   // (512, 512)
    const float* W1b  = (const float*)d_in[3];
    const float* W2w  = (const float*)d_in[4];
    const float* W2b  = (const float*)d_in[5];
    const float* Vw   = (const float*)d_in[6];   // (512, 1)
    // V_b unused: cancels in softmax.

    float* ctx_out  = (float*)d_out;             // (128, 512)
    float* attn_out = (float*)d_out + BB*DD;     // (128, 16, 48, 1)

    static bool attr_set = false;
    if (!attr_set) {
        cudaFuncSetAttribute(score_kernel,
                             cudaFuncAttributeMaxDynamicSharedMemorySize, SMEM_DYN);
        attr_set = true;
    }

    prep_w1_kernel<<<1024, 256>>>(W1w);
    prep_enc_kernel<<<(int)((size_t)MM*DD/4/256), 256>>>(enc);
    dec_proj_kernel<<<BB/4, 512>>>(dec, W2w, W1b, W2b);
    score_kernel<<<(MM/128)*2, 512, SMEM_DYN>>>(Vw);
    softmax_kernel<<<(BB*WW + 127)/128, 128>>>(attn_out);
    context_kernel<<<dim3(BB, 4), 128>>>(enc, attn_out);
    ctx_reduce_kernel<<<64, 256>>>(ctx_out);
}

// round 7
// speedup vs baseline: 2.2035x; 1.3562x over previous
#include <cuda_runtime.h>
#include <cuda_fp16.h>
#include <cstdint>
#include <math.h>

// Problem constants
#define BB 128
#define HH 16
#define WW 48
#define DD 512
#define UU 512
#define HW (HH*WW)          // 768
#define MM (BB*HW)          // 98304

// ---------------------------------------------------------------------------
// Device globals (scratch; no allocation allowed)
// ---------------------------------------------------------------------------
__device__ float  g_dec_proj[BB*UU];          // dec @ W2 + b1 + b2
__device__ float  g_part[2*MM];               // partial scores per N-half
__device__ float  g_ctx_part[4*BB*DD];        // context partials
__device__ __half g_W1T[UU*DD];               // W1^T fp16 [u][k]
__device__ __half g_enc16[(size_t)MM*DD];     // enc fp16 [m][k]

// ---------------------------------------------------------------------------
// Helpers
// ---------------------------------------------------------------------------
__device__ __forceinline__ uint32_t smem_u32(const void* p) {
    uint32_t a;
    asm("{ .reg .u64 t; cvta.to.shared.u64 t, %1; cvt.u32.u64 %0, t; }"
        : "=r"(a) : "l"(p));
    return a;
}

__device__ __forceinline__ void cp16(uint32_t s, const void* g) {
    asm volatile("cp.async.cg.shared.global [%0], [%1], 16;"
                 :: "r"(s), "l"(g) : "memory");
}
__device__ __forceinline__ void cp_commit() {
    asm volatile("cp.async.commit_group;" ::: "memory");
}
#define CP_WAIT(n) asm volatile("cp.async.wait_group %0;" :: "n"(n) : "memory")

__device__ __forceinline__ void ldsm4(uint32_t* r, uint32_t addr) {
    asm volatile("ldmatrix.sync.aligned.m8n8.x4.shared.b16 {%0,%1,%2,%3}, [%4];"
                 : "=r"(r[0]), "=r"(r[1]), "=r"(r[2]), "=r"(r[3]) : "r"(addr));
}

__device__ __forceinline__ void mma_f16(float* c, const uint32_t* a,
                                        uint32_t b0, uint32_t b1) {
    asm volatile("mma.sync.aligned.m16n8k16.row.col.f32.f16.f16.f32 "
                 "{%0,%1,%2,%3}, {%4,%5,%6,%7}, {%8,%9}, {%0,%1,%2,%3};"
                 : "+f"(c[0]), "+f"(c[1]), "+f"(c[2]), "+f"(c[3])
                 : "r"(a[0]), "r"(a[1]), "r"(a[2]), "r"(a[3]),
                   "r"(b0), "r"(b1));
}

// ---------------------------------------------------------------------------
// K0a: W1 -> transposed fp16  (g_W1T[u][k] = fp16(W1[k][u]))
// ---------------------------------------------------------------------------
__global__ void prep_w1_kernel(const float* __restrict__ W1) {
    int idx = blockIdx.x * 256 + threadIdx.x;    // 0..262143
    int k = idx >> 9, u = idx & 511;
    g_W1T[u*DD + k] = __float2half_rn(W1[idx]);
}

// ---------------------------------------------------------------------------
// K0b: enc fp32 -> fp16 (4 elems/thread)
// ---------------------------------------------------------------------------
__global__ __launch_bounds__(256) void prep_enc_kernel(const float* __restrict__ enc) {
    size_t i4 = (size_t)blockIdx.x * 256 + threadIdx.x;  // float4 index
    float4 v = ((const float4*)enc)[i4];
    __half2 h01 = __floats2half2_rn(v.x, v.y);
    __half2 h23 = __floats2half2_rn(v.z, v.w);
    ((uint2*)g_enc16)[i4] = make_uint2(reinterpret_cast<uint32_t&>(h01),
                                       reinterpret_cast<uint32_t&>(h23));
}

// ---------------------------------------------------------------------------
// K1: dec_proj[b,u] = sum_d dec[b,d]*W2[d,u] + W1_b[u] + W2_b[u]
// ---------------------------------------------------------------------------
__global__ __launch_bounds__(512) void dec_proj_kernel(const float* __restrict__ dec,
                                                       const float* __restrict__ W2,
                                                       const float* __restrict__ b1,
                                                       const float* __restrict__ b2) {
    __shared__ float s_dec[4][DD];
    int b0 = blockIdx.x * 4;
    int t = threadIdx.x;
    #pragma unroll
    for (int i = 0; i < 4; i++) s_dec[i][t] = dec[(b0 + i)*DD + t];
    __syncthreads();
    float bias = b1[t] + b2[t];
    float a0 = bias, a1 = bias, a2 = bias, a3 = bias;
    #pragma unroll 8
    for (int d = 0; d < DD; d++) {
        float w = W2[(size_t)d*UU + t];
        a0 += s_dec[0][d] * w;
        a1 += s_dec[1][d] * w;
        a2 += s_dec[2][d] * w;
        a3 += s_dec[3][d] * w;
    }
    g_dec_proj[(b0+0)*UU + t] = a0;
    g_dec_proj[(b0+1)*UU + t] = a1;
    g_dec_proj[(b0+2)*UU + t] = a2;
    g_dec_proj[(b0+3)*UU + t] = a3;
}

// ---------------------------------------------------------------------------
// K2: single-term fp16 score GEMM (mma.sync + ldmatrix) + tanh/V epilogue.
//   CTA: 128 (m) x 256 (n), 512 threads, K-chunk 64.
//   Stage = A 16K + W 32K = 48KB; 4 stages (prefetch depth 3); 1 sync/chunk.
// ---------------------------------------------------------------------------
#define STAGE 49152
#define SMEM_DYN (4*STAGE)   // 192KB

__global__ __launch_bounds__(512, 1) void score_kernel(const float* __restrict__ Vw) {
    extern __shared__ char dsm[];
    __shared__ float dp_s[256];
    __shared__ float vw_s[256];
    __shared__ float s_red[4][128];

    const uint32_t sb = smem_u32(dsm);
    const int tid  = threadIdx.x;
    const int wid  = tid >> 5;
    const int lane = tid & 31;
    const int mtile = blockIdx.x >> 1;
    const int nt    = blockIdx.x & 1;
    const int row0  = mtile * 128;
    const int b     = mtile / 6;          // 6 m-tiles per batch
    const int m0 = (wid >> 2) * 32;       // warp m-offset
    const int n0 = (wid & 3) * 64;        // warp n-offset
    const int rl = lane >> 2;             // fragment row group 0..7
    const int qt = lane & 3;              // fragment col group

    // ldmatrix lane addressing constants (validated rounds 4-6)
    const int sub = lane >> 3, i8 = lane & 7;
    const uint32_t x8   = (uint32_t)i8;
    const uint32_t aRow = (uint32_t)(m0 + ((sub & 1) << 3) + i8) * 128;
    const uint32_t aCS  = (uint32_t)(sub >> 1);
    const uint32_t bRow = (uint32_t)(n0 + ((sub >> 1) << 3) + i8) * 128;
    const uint32_t bCS  = (uint32_t)(sub & 1);

    if (tid < 256) {
        dp_s[tid] = g_dec_proj[b*UU + nt*256 + tid];
        vw_s[tid] = Vw[nt*256 + tid];
    }

    float acc[2][8][4];
    #pragma unroll
    for (int mi = 0; mi < 2; mi++)
        #pragma unroll
        for (int j = 0; j < 8; j++)
            #pragma unroll
            for (int c = 0; c < 4; c++) acc[mi][j][c] = 0.f;

    const __half* __restrict__ Ap = g_enc16 + (size_t)row0*DD;
    const __half* __restrict__ Wp = g_W1T + (size_t)(nt*256)*DD;

    // ---- producer: one K=64 chunk (A + W), all cp.async ----
    auto produce = [&](int kt) {
        const uint32_t as = sb + (uint32_t)(kt & 3)*STAGE;
        const uint32_t ws = as + 16384;
        const int kk = kt * 64;
        #pragma unroll
        for (int i = 0; i < 2; i++) {          // A: 1024 x 16B
            int id = tid + i*512;
            int r = id >> 3, j = id & 7;
            uint32_t off = (uint32_t)r*128 + (uint32_t)((j ^ (r & 7)) << 4);
            cp16(as + off, Ap + (size_t)r*DD + kk + j*8);
        }
        #pragma unroll
        for (int i = 0; i < 4; i++) {          // W: 2048 x 16B
            int id = tid + i*512;
            int r = id >> 3, j = id & 7;
            uint32_t off = (uint32_t)r*128 + (uint32_t)((j ^ (r & 7)) << 4);
            cp16(ws + off, Wp + (size_t)r*DD + kk + j*8);
        }
        cp_commit();
    };

    // ---- prologue: fill 3 of 4 stages ----
    produce(0);
    produce(1);
    produce(2);

    // ---- mainloop: 8 chunks, ONE sync per chunk ----
    #pragma unroll 1
    for (int kt = 0; kt < 8; kt++) {
        if (kt < 6) { CP_WAIT(2); } else if (kt == 6) { CP_WAIT(1); } else { CP_WAIT(0); }
        __syncthreads();                   // chunk kt ready; stage kt-1 drained
        if (kt + 3 < 8) produce(kt + 3);   // overwrites stage consumed at kt-1

        const uint32_t st  = sb + (uint32_t)(kt & 3)*STAGE;
        const uint32_t stW = st + 16384u;
        #pragma unroll
        for (int ks = 0; ks < 4; ks++) {
            uint32_t bq[4][4];
            uint32_t bchunk = (((uint32_t)(2*ks) + bCS) ^ x8) << 4;
            #pragma unroll
            for (int jp = 0; jp < 4; jp++)
                ldsm4(bq[jp], stW + bRow + (uint32_t)jp*2048 + bchunk);
            uint32_t achunk = (((uint32_t)(2*ks) + aCS) ^ x8) << 4;
            uint32_t a0[4], a1[4];
            ldsm4(a0, st + aRow + achunk);
            ldsm4(a1, st + aRow + 2048 + achunk);
            #pragma unroll
            for (int jp = 0; jp < 4; jp++) {
                mma_f16(acc[0][2*jp],   a0, bq[jp][0], bq[jp][1]);
                mma_f16(acc[1][2*jp],   a1, bq[jp][0], bq[jp][1]);
                mma_f16(acc[0][2*jp+1], a0, bq[jp][2], bq[jp][3]);
                mma_f16(acc[1][2*jp+1], a1, bq[jp][2], bq[jp][3]);
            }
        }
    }

    // ---- epilogue: tanh + V-dot ----
    float p[4] = {0.f, 0.f, 0.f, 0.f};
    #pragma unroll
    for (int mi = 0; mi < 2; mi++)
        #pragma unroll
        for (int j = 0; j < 8; j++)
            #pragma unroll
            for (int cc = 0; cc < 4; cc++) {
                int u = n0 + j*8 + qt*2 + (cc & 1);
                int h = cc >> 1;
                p[mi*2 + h] += tanhf(acc[mi][j][cc] + dp_s[u]) * vw_s[u];
            }
    #pragma unroll
    for (int i = 0; i < 4; i++) {
        p[i] += __shfl_xor_sync(0xFFFFFFFF, p[i], 1);
        p[i] += __shfl_xor_sync(0xFFFFFFFF, p[i], 2);
    }
    if (qt == 0) {
        #pragma unroll
        for (int mi = 0; mi < 2; mi++)
            #pragma unroll
            for (int h = 0; h < 2; h++)
                s_red[wid & 3][m0 + mi*16 + h*8 + rl] = p[mi*2 + h];
    }
    __syncthreads();
    if (tid < 128)
        g_part[nt*MM + row0 + tid] =
            (s_red[0][tid] + s_red[1][tid]) + (s_red[2][tid] + s_red[3][tid]);
}

// ---------------------------------------------------------------------------
// K3: softmax over H (axis=1) per (b,w). V_b omitted (shift-invariant).
// ---------------------------------------------------------------------------
__global__ void softmax_kernel(float* __restrict__ attn) {
    int idx = blockIdx.x * blockDim.x + threadIdx.x;
    if (idx >= BB*WW) return;
    int b = idx / WW, w = idx - b*WW;
    const float* p0 = g_part + b*HW + w;
    const float* p1 = g_part + MM + b*HW + w;
    float sc[HH];
    float mx = -1e30f;
    #pragma unroll
    for (int h = 0; h < HH; h++) {
        sc[h] = p0[h*WW] + p1[h*WW];
        mx = fmaxf(mx, sc[h]);
    }
    float sum = 0.f;
    #pragma unroll
    for (int h = 0; h < HH; h++) { sc[h] = __expf(sc[h] - mx); sum += sc[h]; }
    float inv = 1.0f / sum;
    #pragma unroll
    for (int h = 0; h < HH; h++)
        attn[b*HW + h*WW + w] = sc[h] * inv;
}

// ---------------------------------------------------------------------------
// K4: context partials. grid(128,4): block (b,q) sums 192 hw rows.
// ---------------------------------------------------------------------------
__global__ __launch_bounds__(128) void context_kernel(const float* __restrict__ enc,
                                                      const float* __restrict__ attn) {
    __shared__ float s_a[192];
    int b = blockIdx.x, q = blockIdx.y;
    int t = threadIdx.x;                       // owns d = 4t..4t+3
    int base = q * 192;
    for (int i = t; i < 192; i += 128) s_a[i] = attn[b*HW + base + i];
    __syncthreads();
    const float4* __restrict__ e =
        (const float4*)(enc + ((size_t)b*HW + base)*DD) + t;
    float4 a0 = {0,0,0,0}, a1 = a0, a2 = a0, a3 = a0;
    #pragma unroll 4
    for (int i = 0; i < 192; i += 4) {
        float w0 = s_a[i], w1 = s_a[i+1], w2 = s_a[i+2], w3 = s_a[i+3];
        float4 e0 = e[(size_t)(i+0)*128];
        float4 e1 = e[(size_t)(i+1)*128];
        float4 e2 = e[(size_t)(i+2)*128];
        float4 e3 = e[(size_t)(i+3)*128];
        a0.x += w0*e0.x; a0.y += w0*e0.y; a0.z += w0*e0.z; a0.w += w0*e0.w;
        a1.x += w1*e1.x; a1.y += w1*e1.y; a1.z += w1*e1.z; a1.w += w1*e1.w;
        a2.x += w2*e2.x; a2.y += w2*e2.y; a2.z += w2*e2.z; a2.w += w2*e2.w;
        a3.x += w3*e3.x; a3.y += w3*e3.y; a3.z += w3*e3.z; a3.w += w3*e3.w;
    }
    float4 r;
    r.x = (a0.x + a1.x) + (a2.x + a3.x);
    r.y = (a0.y + a1.y) + (a2.y + a3.y);
    r.z = (a0.z + a1.z) + (a2.z + a3.z);
    r.w = (a0.w + a1.w) + (a2.w + a3.w);
    ((float4*)(g_ctx_part + ((size_t)q*BB + b)*DD))[t] = r;
}

__global__ void ctx_reduce_kernel(float* __restrict__ ctx) {
    int i = blockIdx.x * 256 + threadIdx.x;    // 0..16383 float4s
    const float4* p = (const float4*)g_ctx_part;
    float4 a = p[i], b = p[i + 16384], c = p[i + 32768], d = p[i + 49152];
    float4 r;
    r.x = (a.x + b.x) + (c.x + d.x);
    r.y = (a.y + b.y) + (c.y + d.y);
    r.z = (a.z + b.z) + (c.z + d.z);
    r.w = (a.w + b.w) + (c.w + d.w);
    ((float4*)ctx)[i] = r;
}

// ---------------------------------------------------------------------------
extern "C" void kernel_launch(void* const* d_in, const int* in_sizes, int n_in,
                              void* d_out, int out_size) {
    const float* dec  = (const float*)d_in[0];   // (128, 512)
    const float* enc  = (const float*)d_in[1];   // (128, 16, 48, 512)
    const float* W1w  = (const float*)d_in[2];   // (512, 512)
    const float* W1b  = (const float*)d_in[3];
    const float* W2w  = (const float*)d_in[4];
    const float* W2b  = (const float*)d_in[5];
    const float* Vw   = (const float*)d_in[6];   // (512, 1)
    // V_b unused: cancels in softmax.

    float* ctx_out  = (float*)d_out;             // (128, 512)
    float* attn_out = (float*)d_out + BB*DD;     // (128, 16, 48, 1)

    static bool attr_set = false;
    if (!attr_set) {
        cudaFuncSetAttribute(score_kernel,
                             cudaFuncAttributeMaxDynamicSharedMemorySize, SMEM_DYN);
        attr_set = true;
    }

    prep_w1_kernel<<<1024, 256>>>(W1w);
    prep_enc_kernel<<<(int)((size_t)MM*DD/4/256), 256>>>(enc);
    dec_proj_kernel<<<BB/4, 512>>>(dec, W2w, W1b, W2b);
    score_kernel<<<(MM/128)*2, 512, SMEM_DYN>>>(Vw);
    softmax_kernel<<<(BB*WW + 127)/128, 128>>>(attn_out);
    context_kernel<<<dim3(BB, 4), 128>>>(enc, attn_out);
    ctx_reduce_kernel<<<64, 256>>>(ctx_out);
}

// round 8
// speedup vs baseline: 2.3871x; 1.0833x over previous
#include <cuda_runtime.h>
#include <cuda_fp16.h>
#include <cstdint>
#include <math.h>

// Problem constants
#define BB 128
#define HH 16
#define WW 48
#define DD 512
#define UU 512
#define HW (HH*WW)          // 768
#define MM (BB*HW)          // 98304

// ---------------------------------------------------------------------------
// Device globals (scratch; no allocation allowed)
// ---------------------------------------------------------------------------
__device__ float  g_dec_proj[BB*UU];          // dec @ W2 + b1 + b2
__device__ float  g_part[4*MM];               // partial scores per N-quarter
__device__ float  g_ctx_part[4*BB*DD];        // context partials
__device__ __half g_W1T[UU*DD];               // W1^T fp16 [u][k]
__device__ __half g_enc16[(size_t)MM*DD];     // enc fp16 [m][k]

// ---------------------------------------------------------------------------
// Helpers
// ---------------------------------------------------------------------------
__device__ __forceinline__ uint32_t smem_u32(const void* p) {
    uint32_t a;
    asm("{ .reg .u64 t; cvta.to.shared.u64 t, %1; cvt.u32.u64 %0, t; }"
        : "=r"(a) : "l"(p));
    return a;
}

__device__ __forceinline__ void cp16(uint32_t s, const void* g) {
    asm volatile("cp.async.cg.shared.global [%0], [%1], 16;"
                 :: "r"(s), "l"(g) : "memory");
}
__device__ __forceinline__ void cp_commit() {
    asm volatile("cp.async.commit_group;" ::: "memory");
}
#define CP_WAIT(n) asm volatile("cp.async.wait_group %0;" :: "n"(n) : "memory")

__device__ __forceinline__ void ldsm4(uint32_t* r, uint32_t addr) {
    asm volatile("ldmatrix.sync.aligned.m8n8.x4.shared.b16 {%0,%1,%2,%3}, [%4];"
                 : "=r"(r[0]), "=r"(r[1]), "=r"(r[2]), "=r"(r[3]) : "r"(addr));
}

__device__ __forceinline__ void mma_f16(float* c, const uint32_t* a,
                                        uint32_t b0, uint32_t b1) {
    asm volatile("mma.sync.aligned.m16n8k16.row.col.f32.f16.f16.f32 "
                 "{%0,%1,%2,%3}, {%4,%5,%6,%7}, {%8,%9}, {%0,%1,%2,%3};"
                 : "+f"(c[0]), "+f"(c[1]), "+f"(c[2]), "+f"(c[3])
                 : "r"(a[0]), "r"(a[1]), "r"(a[2]), "r"(a[3]),
                   "r"(b0), "r"(b1));
}

// fast tanh: (e^{2x}-1)/(e^{2x}+1), clamped so e^{2x} never overflows
__device__ __forceinline__ float fast_tanh(float x) {
    x = fminf(10.f, fmaxf(-10.f, x));
    float t = __expf(2.f * x);
    return __fdividef(t - 1.f, t + 1.f);
}

// ---------------------------------------------------------------------------
// K0a: W1 -> transposed fp16  (g_W1T[u][k] = fp16(W1[k][u]))
// ---------------------------------------------------------------------------
__global__ void prep_w1_kernel(const float* __restrict__ W1) {
    int idx = blockIdx.x * 256 + threadIdx.x;    // 0..262143
    int k = idx >> 9, u = idx & 511;
    g_W1T[u*DD + k] = __float2half_rn(W1[idx]);
}

// ---------------------------------------------------------------------------
// K0b: enc fp32 -> fp16 (4 elems/thread)
// ---------------------------------------------------------------------------
__global__ __launch_bounds__(256) void prep_enc_kernel(const float* __restrict__ enc) {
    size_t i4 = (size_t)blockIdx.x * 256 + threadIdx.x;  // float4 index
    float4 v = ((const float4*)enc)[i4];
    __half2 h01 = __floats2half2_rn(v.x, v.y);
    __half2 h23 = __floats2half2_rn(v.z, v.w);
    ((uint2*)g_enc16)[i4] = make_uint2(reinterpret_cast<uint32_t&>(h01),
                                       reinterpret_cast<uint32_t&>(h23));
}

// ---------------------------------------------------------------------------
// K1: dec_proj[b,u] = sum_d dec[b,d]*W2[d,u] + W1_b[u] + W2_b[u]
// ---------------------------------------------------------------------------
__global__ __launch_bounds__(512) void dec_proj_kernel(const float* __restrict__ dec,
                                                       const float* __restrict__ W2,
                                                       const float* __restrict__ b1,
                                                       const float* __restrict__ b2) {
    __shared__ float s_dec[4][DD];
    int b0 = blockIdx.x * 4;
    int t = threadIdx.x;
    #pragma unroll
    for (int i = 0; i < 4; i++) s_dec[i][t] = dec[(b0 + i)*DD + t];
    __syncthreads();
    float bias = b1[t] + b2[t];
    float a0 = bias, a1 = bias, a2 = bias, a3 = bias;
    #pragma unroll 8
    for (int d = 0; d < DD; d++) {
        float w = W2[(size_t)d*UU + t];
        a0 += s_dec[0][d] * w;
        a1 += s_dec[1][d] * w;
        a2 += s_dec[2][d] * w;
        a3 += s_dec[3][d] * w;
    }
    g_dec_proj[(b0+0)*UU + t] = a0;
    g_dec_proj[(b0+1)*UU + t] = a1;
    g_dec_proj[(b0+2)*UU + t] = a2;
    g_dec_proj[(b0+3)*UU + t] = a3;
}

// ---------------------------------------------------------------------------
// K2: fp16 score GEMM, 2 CTAs/SM.  CTA tile 128(m) x 128(n), 256 threads,
//   8 warps (4m x 2n, warp tile 32x64). K-chunk 64.
//   Stage = A 16K + W 16K = 32KB; 3 stages = 96KB; 1 sync/chunk.
//   grid = 3072: mtile = bx>>2, nq = bx&3 (n-fast for A L2 reuse).
// ---------------------------------------------------------------------------
#define STAGE 32768
#define SMEM_DYN (3*STAGE)   // 96KB

__global__ __launch_bounds__(256, 2) void score_kernel(const float* __restrict__ Vw) {
    extern __shared__ char dsm[];
    __shared__ float dp_s[128];
    __shared__ float vw_s[128];
    __shared__ float s_red[2][128];

    const uint32_t sb = smem_u32(dsm);
    const int tid  = threadIdx.x;
    const int wid  = tid >> 5;
    const int lane = tid & 31;
    const int mtile = blockIdx.x >> 2;
    const int nq    = blockIdx.x & 3;
    const int row0  = mtile * 128;
    const int b     = mtile / 6;          // 6 m-tiles per batch
    const int m0 = (wid >> 1) * 32;       // warp m-offset (0..96)
    const int n0 = (wid & 1) * 64;        // warp n-offset (0/64)
    const int rl = lane >> 2;             // fragment row group 0..7
    const int qt = lane & 3;              // fragment col group

    // ldmatrix lane addressing constants (validated rounds 4-7)
    const int sub = lane >> 3, i8 = lane & 7;
    const uint32_t x8   = (uint32_t)i8;
    const uint32_t aRow = (uint32_t)(m0 + ((sub & 1) << 3) + i8) * 128;
    const uint32_t aCS  = (uint32_t)(sub >> 1);
    const uint32_t bRow = (uint32_t)(n0 + ((sub >> 1) << 3) + i8) * 128;
    const uint32_t bCS  = (uint32_t)(sub & 1);

    if (tid < 128) {
        dp_s[tid] = g_dec_proj[b*UU + nq*128 + tid];
        vw_s[tid] = Vw[nq*128 + tid];
    }

    float acc[2][8][4];
    #pragma unroll
    for (int mi = 0; mi < 2; mi++)
        #pragma unroll
        for (int j = 0; j < 8; j++)
            #pragma unroll
            for (int c = 0; c < 4; c++) acc[mi][j][c] = 0.f;

    const __half* __restrict__ Ap = g_enc16 + (size_t)row0*DD;
    const __half* __restrict__ Wp = g_W1T + (size_t)(nq*128)*DD;

    // ---- producer: one K=64 chunk (A + W), all cp.async ----
    auto produce = [&](int kt) {
        const uint32_t as = sb + (uint32_t)(kt % 3)*STAGE;
        const uint32_t ws = as + 16384;
        const int kk = kt * 64;
        #pragma unroll
        for (int i = 0; i < 4; i++) {          // A: 1024 x 16B
            int id = tid + i*256;
            int r = id >> 3, j = id & 7;
            uint32_t off = (uint32_t)r*128 + (uint32_t)((j ^ (r & 7)) << 4);
            cp16(as + off, Ap + (size_t)r*DD + kk + j*8);
        }
        #pragma unroll
        for (int i = 0; i < 4; i++) {          // W: 1024 x 16B
            int id = tid + i*256;
            int r = id >> 3, j = id & 7;
            uint32_t off = (uint32_t)r*128 + (uint32_t)((j ^ (r & 7)) << 4);
            cp16(ws + off, Wp + (size_t)r*DD + kk + j*8);
        }
        cp_commit();
    };

    // ---- prologue: fill 2 of 3 stages ----
    produce(0);
    produce(1);

    // ---- mainloop: 8 chunks, ONE sync per chunk ----
    #pragma unroll 1
    for (int kt = 0; kt < 8; kt++) {
        if (kt < 7) { CP_WAIT(1); } else { CP_WAIT(0); }
        __syncthreads();                   // chunk kt ready; stage kt-1 drained
        if (kt + 2 < 8) produce(kt + 2);   // overwrites stage consumed at kt-1

        const uint32_t st  = sb + (uint32_t)(kt % 3)*STAGE;
        const uint32_t stW = st + 16384u;
        #pragma unroll
        for (int ks = 0; ks < 4; ks++) {
            uint32_t bq[4][4];
            uint32_t bchunk = (((uint32_t)(2*ks) + bCS) ^ x8) << 4;
            #pragma unroll
            for (int jp = 0; jp < 4; jp++)
                ldsm4(bq[jp], stW + bRow + (uint32_t)jp*2048 + bchunk);
            uint32_t achunk = (((uint32_t)(2*ks) + aCS) ^ x8) << 4;
            uint32_t a0[4], a1[4];
            ldsm4(a0, st + aRow + achunk);
            ldsm4(a1, st + aRow + 2048 + achunk);
            #pragma unroll
            for (int jp = 0; jp < 4; jp++) {
                mma_f16(acc[0][2*jp],   a0, bq[jp][0], bq[jp][1]);
                mma_f16(acc[1][2*jp],   a1, bq[jp][0], bq[jp][1]);
                mma_f16(acc[0][2*jp+1], a0, bq[jp][2], bq[jp][3]);
                mma_f16(acc[1][2*jp+1], a1, bq[jp][2], bq[jp][3]);
            }
        }
    }

    // ---- epilogue: fast tanh + V-dot ----
    float p[4] = {0.f, 0.f, 0.f, 0.f};
    #pragma unroll
    for (int mi = 0; mi < 2; mi++)
        #pragma unroll
        for (int j = 0; j < 8; j++)
            #pragma unroll
            for (int cc = 0; cc < 4; cc++) {
                int u = n0 + j*8 + qt*2 + (cc & 1);
                int h = cc >> 1;
                p[mi*2 + h] += fast_tanh(acc[mi][j][cc] + dp_s[u]) * vw_s[u];
            }
    #pragma unroll
    for (int i = 0; i < 4; i++) {
        p[i] += __shfl_xor_sync(0xFFFFFFFF, p[i], 1);
        p[i] += __shfl_xor_sync(0xFFFFFFFF, p[i], 2);
    }
    if (qt == 0) {
        #pragma unroll
        for (int mi = 0; mi < 2; mi++)
            #pragma unroll
            for (int h = 0; h < 2; h++)
                s_red[wid & 1][m0 + mi*16 + h*8 + rl] = p[mi*2 + h];
    }
    __syncthreads();
    if (tid < 128)
        g_part[nq*MM + row0 + tid] = s_red[0][tid] + s_red[1][tid];
}

// ---------------------------------------------------------------------------
// K3: softmax over H (axis=1) per (b,w). V_b omitted (shift-invariant).
// ---------------------------------------------------------------------------
__global__ void softmax_kernel(float* __restrict__ attn) {
    int idx = blockIdx.x * blockDim.x + threadIdx.x;
    if (idx >= BB*WW) return;
    int b = idx / WW, w = idx - b*WW;
    const float* p0 = g_part + b*HW + w;
    float sc[HH];
    float mx = -1e30f;
    #pragma unroll
    for (int h = 0; h < HH; h++) {
        sc[h] = (p0[h*WW] + p0[MM + h*WW]) +
                (p0[2*MM + h*WW] + p0[3*MM + h*WW]);
        mx = fmaxf(mx, sc[h]);
    }
    float sum = 0.f;
    #pragma unroll
    for (int h = 0; h < HH; h++) { sc[h] = __expf(sc[h] - mx); sum += sc[h]; }
    float inv = 1.0f / sum;
    #pragma unroll
    for (int h = 0; h < HH; h++)
        attn[b*HW + h*WW + w] = sc[h] * inv;
}

// ---------------------------------------------------------------------------
// K4: context partials. grid(128,4): block (b,q) sums 192 hw rows.
// ---------------------------------------------------------------------------
__global__ __launch_bounds__(128) void context_kernel(const float* __restrict__ enc,
                                                      const float* __restrict__ attn) {
    __shared__ float s_a[192];
    int b = blockIdx.x, q = blockIdx.y;
    int t = threadIdx.x;                       // owns d = 4t..4t+3
    int base = q * 192;
    for (int i = t; i < 192; i += 128) s_a[i] = attn[b*HW + base + i];
    __syncthreads();
    const float4* __restrict__ e =
        (const float4*)(enc + ((size_t)b*HW + base)*DD) + t;
    float4 a0 = {0,0,0,0}, a1 = a0, a2 = a0, a3 = a0;
    #pragma unroll 4
    for (int i = 0; i < 192; i += 4) {
        float w0 = s_a[i], w1 = s_a[i+1], w2 = s_a[i+2], w3 = s_a[i+3];
        float4 e0 = e[(size_t)(i+0)*128];
        float4 e1 = e[(size_t)(i+1)*128];
        float4 e2 = e[(size_t)(i+2)*128];
        float4 e3 = e[(size_t)(i+3)*128];
        a0.x += w0*e0.x; a0.y += w0*e0.y; a0.z += w0*e0.z; a0.w += w0*e0.w;
        a1.x += w1*e1.x; a1.y += w1*e1.y; a1.z += w1*e1.z; a1.w += w1*e1.w;
        a2.x += w2*e2.x; a2.y += w2*e2.y; a2.z += w2*e2.z; a2.w += w2*e2.w;
        a3.x += w3*e3.x; a3.y += w3*e3.y; a3.z += w3*e3.z; a3.w += w3*e3.w;
    }
    float4 r;
    r.x = (a0.x + a1.x) + (a2.x + a3.x);
    r.y = (a0.y + a1.y) + (a2.y + a3.y);
    r.z = (a0.z + a1.z) + (a2.z + a3.z);
    r.w = (a0.w + a1.w) + (a2.w + a3.w);
    ((float4*)(g_ctx_part + ((size_t)q*BB + b)*DD))[t] = r;
}

__global__ void ctx_reduce_kernel(float* __restrict__ ctx) {
    int i = blockIdx.x * 256 + threadIdx.x;    // 0..16383 float4s
    const float4* p = (const float4*)g_ctx_part;
    float4 a = p[i], b = p[i + 16384], c = p[i + 32768], d = p[i + 49152];
    float4 r;
    r.x = (a.x + b.x) + (c.x + d.x);
    r.y = (a.y + b.y) + (c.y + d.y);
    r.z = (a.z + b.z) + (c.z + d.z);
    r.w = (a.w + b.w) + (c.w + d.w);
    ((float4*)ctx)[i] = r;
}

// ---------------------------------------------------------------------------
extern "C" void kernel_launch(void* const* d_in, const int* in_sizes, int n_in,
                              void* d_out, int out_size) {
    const float* dec  = (const float*)d_in[0];   // (128, 512)
    const float* enc  = (const float*)d_in[1];   // (128, 16, 48, 512)
    const float* W1w  = (const float*)d_in[2];   // (512, 512)
    const float* W1b  = (const float*)d_in[3];
    const float* W2w  = (const float*)d_in[4];
    const float* W2b  = (const float*)d_in[5];
    const float* Vw   = (const float*)d_in[6];   // (512, 1)
    // V_b unused: cancels in softmax.

    float* ctx_out  = (float*)d_out;             // (128, 512)
    float* attn_out = (float*)d_out + BB*DD;     // (128, 16, 48, 1)

    static bool attr_set = false;
    if (!attr_set) {
        cudaFuncSetAttribute(score_kernel,
                             cudaFuncAttributeMaxDynamicSharedMemorySize, SMEM_DYN);
        attr_set = true;
    }

    prep_w1_kernel<<<1024, 256>>>(W1w);
    prep_enc_kernel<<<(int)((size_t)MM*DD/4/256), 256>>>(enc);
    dec_proj_kernel<<<BB/4, 512>>>(dec, W2w, W1b, W2b);
    score_kernel<<<(MM/128)*4, 256, SMEM_DYN>>>(Vw);
    softmax_kernel<<<(BB*WW + 127)/128, 128>>>(attn_out);
    context_kernel<<<dim3(BB, 4), 128>>>(enc, attn_out);
    ctx_reduce_kernel<<<64, 256>>>(ctx_out);
}

// round 9
// speedup vs baseline: 2.6099x; 1.0933x over previous
#include <cuda_runtime.h>
#include <cuda_fp16.h>
#include <cstdint>
#include <math.h>

// Problem constants
#define BB 128
#define HH 16
#define WW 48
#define DD 512
#define UU 512
#define HW (HH*WW)          // 768
#define MM (BB*HW)          // 98304

// ---------------------------------------------------------------------------
// Device globals (scratch; no allocation allowed)
// ---------------------------------------------------------------------------
__device__ float  g_dec_proj[BB*UU];          // dec @ W2 + b1 + b2
__device__ float  g_part[4*MM];               // partial scores per N-quarter
__device__ float  g_ctx_part[8*BB*DD];        // context partials
__device__ __half g_W1T[UU*DD];               // W1^T fp16 [u][k]
__device__ __half g_enc16[(size_t)MM*DD];     // enc fp16 [m][k]

// ---------------------------------------------------------------------------
// Helpers
// ---------------------------------------------------------------------------
__device__ __forceinline__ uint32_t smem_u32(const void* p) {
    uint32_t a;
    asm("{ .reg .u64 t; cvta.to.shared.u64 t, %1; cvt.u32.u64 %0, t; }"
        : "=r"(a) : "l"(p));
    return a;
}

__device__ __forceinline__ void cp16(uint32_t s, const void* g) {
    asm volatile("cp.async.cg.shared.global [%0], [%1], 16;"
                 :: "r"(s), "l"(g) : "memory");
}
__device__ __forceinline__ void cp_commit() {
    asm volatile("cp.async.commit_group;" ::: "memory");
}
#define CP_WAIT(n) asm volatile("cp.async.wait_group %0;" :: "n"(n) : "memory")

__device__ __forceinline__ void ldsm4(uint32_t* r, uint32_t addr) {
    asm volatile("ldmatrix.sync.aligned.m8n8.x4.shared.b16 {%0,%1,%2,%3}, [%4];"
                 : "=r"(r[0]), "=r"(r[1]), "=r"(r[2]), "=r"(r[3]) : "r"(addr));
}

__device__ __forceinline__ void mma_f16(float* c, const uint32_t* a,
                                        uint32_t b0, uint32_t b1) {
    asm volatile("mma.sync.aligned.m16n8k16.row.col.f32.f16.f16.f32 "
                 "{%0,%1,%2,%3}, {%4,%5,%6,%7}, {%8,%9}, {%0,%1,%2,%3};"
                 : "+f"(c[0]), "+f"(c[1]), "+f"(c[2]), "+f"(c[3])
                 : "r"(a[0]), "r"(a[1]), "r"(a[2]), "r"(a[3]),
                   "r"(b0), "r"(b1));
}

// fast tanh: (e^{2x}-1)/(e^{2x}+1), clamped so e^{2x} never overflows
__device__ __forceinline__ float fast_tanh(float x) {
    x = fminf(10.f, fmaxf(-10.f, x));
    float t = __expf(2.f * x);
    return __fdividef(t - 1.f, t + 1.f);
}

// ---------------------------------------------------------------------------
// K0a: W1 -> transposed fp16  (g_W1T[u][k] = fp16(W1[k][u]))
// ---------------------------------------------------------------------------
__global__ void prep_w1_kernel(const float* __restrict__ W1) {
    int idx = blockIdx.x * 256 + threadIdx.x;    // 0..262143
    int k = idx >> 9, u = idx & 511;
    g_W1T[u*DD + k] = __float2half_rn(W1[idx]);
}

// ---------------------------------------------------------------------------
// K0b: enc fp32 -> fp16 (4 elems/thread)
// ---------------------------------------------------------------------------
__global__ __launch_bounds__(256) void prep_enc_kernel(const float* __restrict__ enc) {
    size_t i4 = (size_t)blockIdx.x * 256 + threadIdx.x;  // float4 index
    float4 v = ((const float4*)enc)[i4];
    __half2 h01 = __floats2half2_rn(v.x, v.y);
    __half2 h23 = __floats2half2_rn(v.z, v.w);
    ((uint2*)g_enc16)[i4] = make_uint2(reinterpret_cast<uint32_t&>(h01),
                                       reinterpret_cast<uint32_t&>(h23));
}

// ---------------------------------------------------------------------------
// K1: dec_proj[b,u] = sum_d dec[b,d]*W2[d,u] + W1_b[u] + W2_b[u]
// ---------------------------------------------------------------------------
__global__ __launch_bounds__(512) void dec_proj_kernel(const float* __restrict__ dec,
                                                       const float* __restrict__ W2,
                                                       const float* __restrict__ b1,
                                                       const float* __restrict__ b2) {
    __shared__ float s_dec[4][DD];
    int b0 = blockIdx.x * 4;
    int t = threadIdx.x;
    #pragma unroll
    for (int i = 0; i < 4; i++) s_dec[i][t] = dec[(b0 + i)*DD + t];
    __syncthreads();
    float bias = b1[t] + b2[t];
    float a0 = bias, a1 = bias, a2 = bias, a3 = bias;
    #pragma unroll 8
    for (int d = 0; d < DD; d++) {
        float w = W2[(size_t)d*UU + t];
        a0 += s_dec[0][d] * w;
        a1 += s_dec[1][d] * w;
        a2 += s_dec[2][d] * w;
        a3 += s_dec[3][d] * w;
    }
    g_dec_proj[(b0+0)*UU + t] = a0;
    g_dec_proj[(b0+1)*UU + t] = a1;
    g_dec_proj[(b0+2)*UU + t] = a2;
    g_dec_proj[(b0+3)*UU + t] = a3;
}

// ---------------------------------------------------------------------------
// K2: fp16 score GEMM, 2 CTAs/SM.  CTA tile 128(m) x 128(n), 256 threads,
//   8 warps (4m x 2n, warp tile 32x64). K-chunk 64.
//   Stage = A 16K + W 16K = 32KB; 3 stages = 96KB; 1 sync/chunk.
//   grid = 3072: mtile = bx>>2, nq = bx&3 (n-fast for A L2 reuse).
// ---------------------------------------------------------------------------
#define STAGE 32768
#define SMEM_DYN (3*STAGE)   // 96KB

__global__ __launch_bounds__(256, 2) void score_kernel(const float* __restrict__ Vw) {
    extern __shared__ char dsm[];
    __shared__ float dp_s[128];
    __shared__ float vw_s[128];
    __shared__ float s_red[2][128];

    const uint32_t sb = smem_u32(dsm);
    const int tid  = threadIdx.x;
    const int wid  = tid >> 5;
    const int lane = tid & 31;
    const int mtile = blockIdx.x >> 2;
    const int nq    = blockIdx.x & 3;
    const int row0  = mtile * 128;
    const int b     = mtile / 6;          // 6 m-tiles per batch
    const int m0 = (wid >> 1) * 32;       // warp m-offset (0..96)
    const int n0 = (wid & 1) * 64;        // warp n-offset (0/64)
    const int rl = lane >> 2;             // fragment row group 0..7
    const int qt = lane & 3;              // fragment col group

    // ldmatrix lane addressing constants (validated rounds 4-8)
    const int sub = lane >> 3, i8 = lane & 7;
    const uint32_t x8   = (uint32_t)i8;
    const uint32_t aRow = (uint32_t)(m0 + ((sub & 1) << 3) + i8) * 128;
    const uint32_t aCS  = (uint32_t)(sub >> 1);
    const uint32_t bRow = (uint32_t)(n0 + ((sub >> 1) << 3) + i8) * 128;
    const uint32_t bCS  = (uint32_t)(sub & 1);

    // hoisted per-ks swizzled chunk offsets (loop-invariant across chunks)
    uint32_t aChunk[4], bChunk[4];
    #pragma unroll
    for (int ks = 0; ks < 4; ks++) {
        aChunk[ks] = (((uint32_t)(2*ks) + aCS) ^ x8) << 4;
        bChunk[ks] = (((uint32_t)(2*ks) + bCS) ^ x8) << 4;
    }

    if (tid < 128) {
        dp_s[tid] = g_dec_proj[b*UU + nq*128 + tid];
        vw_s[tid] = Vw[nq*128 + tid];
    }

    float acc[2][8][4];
    #pragma unroll
    for (int mi = 0; mi < 2; mi++)
        #pragma unroll
        for (int j = 0; j < 8; j++)
            #pragma unroll
            for (int c = 0; c < 4; c++) acc[mi][j][c] = 0.f;

    const __half* __restrict__ Ap = g_enc16 + (size_t)row0*DD;
    const __half* __restrict__ Wp = g_W1T + (size_t)(nq*128)*DD;

    // ---- producer: one K=64 chunk (A + W), all cp.async ----
    auto produce = [&](int kt) {
        const uint32_t as = sb + (uint32_t)(kt % 3)*STAGE;
        const uint32_t ws = as + 16384;
        const int kk = kt * 64;
        #pragma unroll
        for (int i = 0; i < 4; i++) {          // A: 1024 x 16B
            int id = tid + i*256;
            int r = id >> 3, j = id & 7;
            uint32_t off = (uint32_t)r*128 + (uint32_t)((j ^ (r & 7)) << 4);
            cp16(as + off, Ap + (size_t)r*DD + kk + j*8);
        }
        #pragma unroll
        for (int i = 0; i < 4; i++) {          // W: 1024 x 16B
            int id = tid + i*256;
            int r = id >> 3, j = id & 7;
            uint32_t off = (uint32_t)r*128 + (uint32_t)((j ^ (r & 7)) << 4);
            cp16(ws + off, Wp + (size_t)r*DD + kk + j*8);
        }
        cp_commit();
    };

    // ---- prologue: fill 2 of 3 stages ----
    produce(0);
    produce(1);

    // ---- mainloop: 8 chunks, ONE sync per chunk ----
    #pragma unroll 1
    for (int kt = 0; kt < 8; kt++) {
        if (kt < 7) { CP_WAIT(1); } else { CP_WAIT(0); }
        __syncthreads();                   // chunk kt ready; stage kt-1 drained
        if (kt + 2 < 8) produce(kt + 2);   // overwrites stage consumed at kt-1

        const uint32_t st  = sb + (uint32_t)(kt % 3)*STAGE;
        const uint32_t stW = st + 16384u;
        #pragma unroll
        for (int ks = 0; ks < 4; ks++) {
            uint32_t bq[4][4];
            #pragma unroll
            for (int jp = 0; jp < 4; jp++)
                ldsm4(bq[jp], stW + bRow + (uint32_t)jp*2048 + bChunk[ks]);
            uint32_t a0[4], a1[4];
            ldsm4(a0, st + aRow + aChunk[ks]);
            ldsm4(a1, st + aRow + 2048 + aChunk[ks]);
            #pragma unroll
            for (int jp = 0; jp < 4; jp++) {
                mma_f16(acc[0][2*jp],   a0, bq[jp][0], bq[jp][1]);
                mma_f16(acc[1][2*jp],   a1, bq[jp][0], bq[jp][1]);
                mma_f16(acc[0][2*jp+1], a0, bq[jp][2], bq[jp][3]);
                mma_f16(acc[1][2*jp+1], a1, bq[jp][2], bq[jp][3]);
            }
        }
    }

    // ---- epilogue: fast tanh + V-dot ----
    float p[4] = {0.f, 0.f, 0.f, 0.f};
    #pragma unroll
    for (int mi = 0; mi < 2; mi++)
        #pragma unroll
        for (int j = 0; j < 8; j++)
            #pragma unroll
            for (int cc = 0; cc < 4; cc++) {
                int u = n0 + j*8 + qt*2 + (cc & 1);
                int h = cc >> 1;
                p[mi*2 + h] += fast_tanh(acc[mi][j][cc] + dp_s[u]) * vw_s[u];
            }
    #pragma unroll
    for (int i = 0; i < 4; i++) {
        p[i] += __shfl_xor_sync(0xFFFFFFFF, p[i], 1);
        p[i] += __shfl_xor_sync(0xFFFFFFFF, p[i], 2);
    }
    if (qt == 0) {
        #pragma unroll
        for (int mi = 0; mi < 2; mi++)
            #pragma unroll
            for (int h = 0; h < 2; h++)
                s_red[wid & 1][m0 + mi*16 + h*8 + rl] = p[mi*2 + h];
    }
    __syncthreads();
    if (tid < 128)
        g_part[nq*MM + row0 + tid] = s_red[0][tid] + s_red[1][tid];
}

// ---------------------------------------------------------------------------
// K3: softmax over H (axis=1) per (b,w). V_b omitted (shift-invariant).
// ---------------------------------------------------------------------------
__global__ void softmax_kernel(float* __restrict__ attn) {
    int idx = blockIdx.x * blockDim.x + threadIdx.x;
    if (idx >= BB*WW) return;
    int b = idx / WW, w = idx - b*WW;
    const float* p0 = g_part + b*HW + w;
    float sc[HH];
    float mx = -1e30f;
    #pragma unroll
    for (int h = 0; h < HH; h++) {
        sc[h] = (p0[h*WW] + p0[MM + h*WW]) +
                (p0[2*MM + h*WW] + p0[3*MM + h*WW]);
        mx = fmaxf(mx, sc[h]);
    }
    float sum = 0.f;
    #pragma unroll
    for (int h = 0; h < HH; h++) { sc[h] = __expf(sc[h] - mx); sum += sc[h]; }
    float inv = 1.0f / sum;
    #pragma unroll
    for (int h = 0; h < HH; h++)
        attn[b*HW + h*WW + w] = sc[h] * inv;
}

// ---------------------------------------------------------------------------
// K4: context partials from fp16 enc. grid(128,8): block (b,q) sums 96 rows.
// ---------------------------------------------------------------------------
__global__ __launch_bounds__(128) void context_kernel(const float* __restrict__ attn) {
    __shared__ float s_a[96];
    int b = blockIdx.x, q = blockIdx.y;
    int t = threadIdx.x;                       // owns d = 4t..4t+3
    int base = q * 96;
    if (t < 96) s_a[t] = attn[b*HW + base + t];
    __syncthreads();
    const uint2* __restrict__ e =
        (const uint2*)(g_enc16 + ((size_t)b*HW + base)*DD) + t;   // 4 halves/thread
    float4 a0 = {0,0,0,0}, a1 = a0, a2 = a0, a3 = a0;
    #pragma unroll 4
    for (int i = 0; i < 96; i += 4) {
        float w0 = s_a[i], w1 = s_a[i+1], w2 = s_a[i+2], w3 = s_a[i+3];
        uint2 v0 = e[(size_t)(i+0)*128];
        uint2 v1 = e[(size_t)(i+1)*128];
        uint2 v2 = e[(size_t)(i+2)*128];
        uint2 v3 = e[(size_t)(i+3)*128];
        float2 f0a = __half22float2(reinterpret_cast<__half2&>(v0.x));
        float2 f0b = __half22float2(reinterpret_cast<__half2&>(v0.y));
        float2 f1a = __half22float2(reinterpret_cast<__half2&>(v1.x));
        float2 f1b = __half22float2(reinterpret_cast<__half2&>(v1.y));
        float2 f2a = __half22float2(reinterpret_cast<__half2&>(v2.x));
        float2 f2b = __half22float2(reinterpret_cast<__half2&>(v2.y));
        float2 f3a = __half22float2(reinterpret_cast<__half2&>(v3.x));
        float2 f3b = __half22float2(reinterpret_cast<__half2&>(v3.y));
        a0.x += w0*f0a.x; a0.y += w0*f0a.y; a0.z += w0*f0b.x; a0.w += w0*f0b.y;
        a1.x += w1*f1a.x; a1.y += w1*f1a.y; a1.z += w1*f1b.x; a1.w += w1*f1b.y;
        a2.x += w2*f2a.x; a2.y += w2*f2a.y; a2.z += w2*f2b.x; a2.w += w2*f2b.y;
        a3.x += w3*f3a.x; a3.y += w3*f3a.y; a3.z += w3*f3b.x; a3.w += w3*f3b.y;
    }
    float4 r;
    r.x = (a0.x + a1.x) + (a2.x + a3.x);
    r.y = (a0.y + a1.y) + (a2.y + a3.y);
    r.z = (a0.z + a1.z) + (a2.z + a3.z);
    r.w = (a0.w + a1.w) + (a2.w + a3.w);
    ((float4*)(g_ctx_part + ((size_t)q*BB + b)*DD))[t] = r;
}

__global__ void ctx_reduce_kernel(float* __restrict__ ctx) {
    int i = blockIdx.x * 256 + threadIdx.x;    // 0..16383 float4s
    const float4* p = (const float4*)g_ctx_part;
    float4 r = {0, 0, 0, 0};
    #pragma unroll
    for (int j = 0; j < 8; j++) {
        float4 v = p[i + j*16384];
        r.x += v.x; r.y += v.y; r.z += v.z; r.w += v.w;
    }
    ((float4*)ctx)[i] = r;
}

// ---------------------------------------------------------------------------
extern "C" void kernel_launch(void* const* d_in, const int* in_sizes, int n_in,
                              void* d_out, int out_size) {
    const float* dec  = (const float*)d_in[0];   // (128, 512)
    const float* enc  = (const float*)d_in[1];   // (128, 16, 48, 512)
    const float* W1w  = (const float*)d_in[2];   // (512, 512)
    const float* W1b  = (const float*)d_in[3];
    const float* W2w  = (const float*)d_in[4];
    const float* W2b  = (const float*)d_in[5];
    const float* Vw   = (const float*)d_in[6];   // (512, 1)
    // V_b unused: cancels in softmax.

    float* ctx_out  = (float*)d_out;             // (128, 512)
    float* attn_out = (float*)d_out + BB*DD;     // (128, 16, 48, 1)

    static bool attr_set = false;
    if (!attr_set) {
        cudaFuncSetAttribute(score_kernel,
                             cudaFuncAttributeMaxDynamicSharedMemorySize, SMEM_DYN);
        attr_set = true;
    }

    prep_w1_kernel<<<1024, 256>>>(W1w);
    prep_enc_kernel<<<(int)((size_t)MM*DD/4/256), 256>>>(enc);
    dec_proj_kernel<<<BB/4, 512>>>(dec, W2w, W1b, W2b);
    score_kernel<<<(MM/128)*4, 256, SMEM_DYN>>>(Vw);
    softmax_kernel<<<(BB*WW + 127)/128, 128>>>(attn_out);
    context_kernel<<<dim3(BB, 8), 128>>>(attn_out);
    ctx_reduce_kernel<<<64, 256>>>(ctx_out);
}